// round 10
// baseline (speedup 1.0000x reference)
#include <cuda_runtime.h>
#include <math.h>

// ---------------- problem constants ----------------
#define BATCH 4
#define TLEN  131072          // waveform length
#define T1    32768           // after conv1 (stride 4)
#define T2    8192            // after conv2 (stride 4)
#define DCH   128             // channels / code dim
#define KCODE 2048            // codebook size
#define NROWS (BATCH*T2)      // 32768 VQ rows

#define XR_OFF  3
#define IDX_OFF (3 + BATCH*TLEN)   // 3 + 524288

typedef unsigned long long ull;

// ---------------- scratch (device globals; no cudaMalloc allowed) ----------------
// NOTE: never pass these as kernel arguments from host code (host shadow symbol
// trap on ATS systems) — always reference them directly from device code.
__device__ float g_buf1[BATCH*DCH*T1];   // z1, later reused as decoder upsample-1 output
__device__ float g_z2 [BATCH*DCH*T2];
__device__ float g_z  [BATCH*DCH*T2];    // raw z, d-major (for commitment loss)
__device__ float g_znt[NROWS*DCH];       // normalized z, t-major [row][d]
__device__ float g_zq [BATCH*DCH*T2];
__device__ float g_h  [BATCH*DCH*T2];
__device__ float g_embnT[DCH*KCODE];     // normalized embedding, TRANSPOSED [d][e]
__device__ int   g_idx[NROWS];
__device__ double g_acc[2];              // [0]=rec sum, [1]=com sum

__device__ __forceinline__ float gelu_exact(float v) {
    return 0.5f * v * (1.0f + erff(v * 0.70710678118654752440f));
}

// ---------------- packed f32x2 helpers (Blackwell FFMA2) ----------------
__device__ __forceinline__ ull f2_fma(ull a, ull b, ull c) {
    ull d;
    asm("fma.rn.f32x2 %0, %1, %2, %3;" : "=l"(d) : "l"(a), "l"(b), "l"(c));
    return d;
}
__device__ __forceinline__ ull f2_dup(float v) {
    ull d;
    asm("mov.b64 %0, {%1, %1};" : "=l"(d) : "f"(v));
    return d;
}
__device__ __forceinline__ ull f2_pack(float lo, float hi) {
    ull d;
    asm("mov.b64 %0, {%1, %2};" : "=l"(d) : "f"(lo), "f"(hi));
    return d;
}
__device__ __forceinline__ void f2_unpack(ull p, float& lo, float& hi) {
    asm("mov.b64 {%0, %1}, %2;" : "=f"(lo), "=f"(hi) : "l"(p));
}

// ---------------- zero accumulators ----------------
__global__ void k_zero() {
    if (threadIdx.x < 2) g_acc[threadIdx.x] = 0.0;
}

// ---------------- conv1: [B,1,T] -> gelu -> [B,128,T1], k=8, s=4, p=2 ----------------
__global__ void k_conv1(const float* __restrict__ x, const float* __restrict__ w,
                        const float* __restrict__ bias) {
    __shared__ float sx[1032];
    __shared__ float sw[1024];
    __shared__ float sb[128];
    const int b  = blockIdx.y;
    const int t0 = blockIdx.x * 256;
    const int in0 = 4 * t0 - 2;
    for (int i = threadIdx.x; i < 1032; i += 256) {
        int p = in0 + i;
        sx[i] = (p >= 0 && p < TLEN) ? x[b * TLEN + p] : 0.f;
    }
    for (int i = threadIdx.x; i < 1024; i += 256) sw[i] = w[i];
    if (threadIdx.x < 128) sb[threadIdx.x] = bias[threadIdx.x];
    __syncthreads();
    const int t = threadIdx.x;
    for (int c = 0; c < 128; ++c) {
        float a = sb[c];
        #pragma unroll
        for (int j = 0; j < 8; ++j) a += sw[c * 8 + j] * sx[4 * t + j];
        g_buf1[((size_t)(b * DCH + c)) * T1 + t0 + t] = gelu_exact(a);
    }
}

// ---------------- conv2 (FFMA2, smem-paired weights): [B,128,T1] -> gelu -> [B,128,T2] --
// 16 chunks of 8 ci (4 ci-pairs). Weights staged PRE-PAIRED (even-ci, odd-ci) as ull in
// smem; inner loop = pure LDS + FFMA2 (no packing movs, no scattered weight LDG).
// acc lo = even-ci partial, hi = odd-ci partial; combined at the end.
__global__ __launch_bounds__(128) void k_conv2(const float* __restrict__ w,
                                               const float* __restrict__ bias) {
    __shared__ float sin2[4 * 136];    // 4 ci-pairs x 68 positions x 2 interleaved (2.2KB)
    __shared__ ull   swp[32 * 129];    // 4 pairs x 8 taps, [r][c] pre-paired (33KB)
    const int b  = blockIdx.y;
    const int t0 = blockIdx.x * 16;
    const int in0 = 4 * t0 - 2;
    const int c = threadIdx.x;
    ull acc2[16];
    #pragma unroll
    for (int t = 0; t < 16; ++t) acc2[t] = 0ull;

    for (int cc = 0; cc < 16; ++cc) {
        __syncthreads();   // previous chunk fully consumed
        // input chunk: local ci l = 0..7 (global ci = cc*8 + l), pair-interleaved
        for (int i = threadIdx.x; i < 8 * 68; i += 128) {
            int l = i / 68, li = i % 68;
            int ci = cc * 8 + l;
            int p = in0 + li;
            float v = (p >= 0 && p < T1) ? g_buf1[((size_t)(b * DCH + ci)) * T1 + p] : 0.f;
            sin2[(l >> 1) * 136 + li * 2 + (l & 1)] = v;
        }
        // weights pre-paired: swp[(m*8+k)*129 + cw] = (w[cw][cc*8+2m][k], w[cw][cc*8+2m+1][k])
        for (int i = threadIdx.x; i < 4096; i += 128) {
            int r  = i & 31;         // m*8 + k
            int cw = i >> 5;         // 4 c per pass
            int m  = r >> 3, k = r & 7;
            const float* wp = w + (size_t)cw * 1024 + cc * 64 + m * 16 + k;
            swp[r * 129 + cw] = f2_pack(wp[0], wp[8]);
        }
        __syncthreads();
        #pragma unroll
        for (int m = 0; m < 4; ++m) {
            ull pk[8];
            #pragma unroll
            for (int k = 0; k < 8; ++k) pk[k] = swp[(m * 8 + k) * 129 + c];
            const ulonglong2* row2 = (const ulonglong2*)(sin2 + m * 136);
            ulonglong2 pA = row2[0];     // positions 0,1
            ulonglong2 pB = row2[1];     // positions 2,3
            #pragma unroll
            for (int t = 0; t < 16; ++t) {
                ulonglong2 pC = row2[2 * t + 2];   // positions 4t+4, 4t+5
                ulonglong2 pD = row2[2 * t + 3];   // positions 4t+6, 4t+7
                acc2[t] = f2_fma(pA.x, pk[0], acc2[t]);
                acc2[t] = f2_fma(pA.y, pk[1], acc2[t]);
                acc2[t] = f2_fma(pB.x, pk[2], acc2[t]);
                acc2[t] = f2_fma(pB.y, pk[3], acc2[t]);
                acc2[t] = f2_fma(pC.x, pk[4], acc2[t]);
                acc2[t] = f2_fma(pC.y, pk[5], acc2[t]);
                acc2[t] = f2_fma(pD.x, pk[6], acc2[t]);
                acc2[t] = f2_fma(pD.y, pk[7], acc2[t]);
                pA = pC; pB = pD;
            }
        }
    }
    float* outp = g_z2 + ((size_t)(b * DCH + c)) * T2 + t0;
    float bv = bias[c];
    #pragma unroll
    for (int t = 0; t < 16; ++t) {
        float lo, hi;
        f2_unpack(acc2[t], lo, hi);
        outp[t] = gelu_exact(bv + lo + hi);
    }
}

// ---------------- k3 conv (s=1, p=1), smem-staged weights, 256 threads ----------------
// STAGE 0: enc conv3, g_z2 -> g_z (raw, d-major) + g_znt (L2-normalized, t-major)
// STAGE 1: dec conv0, g_zq -> gelu -> g_h
template <int STAGE>
__global__ __launch_bounds__(256) void k_conv3(const float* __restrict__ w,
                                               const float* __restrict__ bias) {
    const float* __restrict__ in = (STAGE == 0) ? g_z2 : g_zq;
    __shared__ float s[128 * 36];      // input, span 34 padded to 36; reused for norm overlay
    __shared__ float swt[48 * 129];    // weight chunk: 16 ci x 3 taps, transposed [r][c]
    __shared__ float sinv[32];
    const int b  = blockIdx.y;
    const int t0 = blockIdx.x * 32;
    const int in0 = t0 - 1;
    for (int i = threadIdx.x; i < 128 * 34; i += 256) {
        int ci = i / 34, li = i % 34;
        int p = in0 + li;
        s[ci * 36 + li] = (p >= 0 && p < T2) ? in[((size_t)(b * DCH + ci)) * T2 + p] : 0.f;
    }
    const int c = threadIdx.x & 127;
    const int h = threadIdx.x >> 7;
    float acc[16];
    {
        float bv = bias[c];
        #pragma unroll
        for (int t = 0; t < 16; ++t) acc[t] = bv;
    }
    for (int cc = 0; cc < 8; ++cc) {
        __syncthreads();   // prior chunk reads done (and input stores on first iter)
        for (int i = threadIdx.x; i < 6144; i += 256) {
            int wc = i / 48, r = i - wc * 48;
            swt[r * 129 + wc] = w[wc * 384 + cc * 48 + r];
        }
        __syncthreads();
        #pragma unroll
        for (int cil = 0; cil < 16; ++cil) {
            const int ci = cc * 16 + cil;
            float w0 = swt[(cil * 3 + 0) * 129 + c];
            float w1 = swt[(cil * 3 + 1) * 129 + c];
            float w2 = swt[(cil * 3 + 2) * 129 + c];
            const float4* row4 = (const float4*)(s + ci * 36) + 4 * h;
            float f[20];
            #pragma unroll
            for (int q = 0; q < 5; ++q) {
                float4 v = row4[q];
                f[q * 4 + 0] = v.x; f[q * 4 + 1] = v.y; f[q * 4 + 2] = v.z; f[q * 4 + 3] = v.w;
            }
            #pragma unroll
            for (int t = 0; t < 16; ++t)
                acc[t] = fmaf(w0, f[t], fmaf(w1, f[t + 1], fmaf(w2, f[t + 2], acc[t])));
        }
    }
    if (STAGE == 1) {
        float* outp = g_h + ((size_t)(b * DCH + c)) * T2 + t0 + 16 * h;
        #pragma unroll
        for (int t = 0; t < 16; ++t) outp[t] = gelu_exact(acc[t]);
        return;
    }
    // STAGE 0: fused row normalization across channels (block owns all 128 c)
    __syncthreads();   // everyone done reading s
    #pragma unroll
    for (int t = 0; t < 16; ++t) s[(16 * h + t) * 132 + c] = acc[t] * acc[t];
    __syncthreads();
    if (threadIdx.x < 128) {
        const int t = threadIdx.x >> 2;
        const int q = threadIdx.x & 3;
        float sm = 0.f;
        #pragma unroll
        for (int j = 0; j < 32; ++j) sm += s[t * 132 + q * 32 + j];
        sm += __shfl_xor_sync(0xffffffffu, sm, 1);
        sm += __shfl_xor_sync(0xffffffffu, sm, 2);
        if (q == 0) sinv[t] = 1.0f / fmaxf(sqrtf(sm), 1e-12f);
    }
    __syncthreads();
    {
        float* outp = g_z + ((size_t)(b * DCH + c)) * T2 + t0 + 16 * h;
        #pragma unroll
        for (int t = 0; t < 16; ++t) {
            outp[t] = acc[t];
            g_znt[(size_t)(b * T2 + t0 + 16 * h + t) * DCH + c] = acc[t] * sinv[16 * h + t];
        }
    }
}

// ---------------- normalize embedding rows, store transposed [d][e] ----------------
__global__ void k_embnorm(const float* __restrict__ emb) {
    const int e    = blockIdx.x * 8 + (threadIdx.x >> 5);
    const int lane = threadIdx.x & 31;
    float4 v = *(const float4*)(emb + (size_t)e * DCH + lane * 4);
    float ss = v.x * v.x + v.y * v.y + v.z * v.z + v.w * v.w;
    #pragma unroll
    for (int o = 16; o > 0; o >>= 1) ss += __shfl_xor_sync(0xffffffffu, ss, o);
    float inv = 1.0f / fmaxf(sqrtf(ss), 1e-12f);
    g_embnT[(size_t)(lane * 4 + 0) * KCODE + e] = v.x * inv;
    g_embnT[(size_t)(lane * 4 + 1) * KCODE + e] = v.y * inv;
    g_embnT[(size_t)(lane * 4 + 2) * KCODE + e] = v.z * inv;
    g_embnT[(size_t)(lane * 4 + 3) * KCODE + e] = v.w * inv;
}

// ---------------- VQ GEMM + argmax, packed f32x2 (kept from R4 — proven win) ----------
__global__ __launch_bounds__(256) void k_vqgemm() {
    __shared__ float sA[128 * 64];   // [k][row] 32KB
    __shared__ float sB[16 * 128];   // [kk][c]   8KB
    const int tx   = threadIdx.x;
    const int row0 = blockIdx.x * 64;
    for (int it = tx; it < 2048; it += 256) {
        int row = it & 63, kq = it >> 6;
        float4 v = *(const float4*)&g_znt[(size_t)(row0 + row) * DCH + kq * 4];
        sA[(kq * 4 + 0) * 64 + row] = v.x;
        sA[(kq * 4 + 1) * 64 + row] = v.y;
        sA[(kq * 4 + 2) * 64 + row] = v.z;
        sA[(kq * 4 + 3) * 64 + row] = v.w;
    }
    const int tr = tx >> 5;
    const int tc = tx & 31;
    float best[8];
    int   bidx[8];
    #pragma unroll
    for (int i = 0; i < 8; ++i) { best[i] = -1e30f; bidx[i] = 0; }

    for (int ct = 0; ct < KCODE / 128; ++ct) {
        ull acc[4][4];
        #pragma unroll
        for (int p = 0; p < 4; ++p)
            #pragma unroll
            for (int j = 0; j < 4; ++j) acc[p][j] = 0ull;
        for (int kc = 0; kc < 8; ++kc) {
            __syncthreads();
            for (int it = tx; it < 512; it += 256) {
                int kk = it >> 5, c4 = it & 31;
                *(float4*)&sB[kk * 128 + c4 * 4] =
                    *(const float4*)&g_embnT[(size_t)(kc * 16 + kk) * KCODE + ct * 128 + c4 * 4];
            }
            __syncthreads();
            #pragma unroll 4
            for (int kk = 0; kk < 16; ++kk) {
                const int k = kc * 16 + kk;
                ulonglong2 aA = *(const ulonglong2*)&sA[k * 64 + tr * 8];
                ulonglong2 aB = *(const ulonglong2*)&sA[k * 64 + tr * 8 + 4];
                float4 bv = *(const float4*)&sB[kk * 128 + tc * 4];
                ull b0 = f2_dup(bv.x), b1 = f2_dup(bv.y);
                ull b2 = f2_dup(bv.z), b3 = f2_dup(bv.w);
                acc[0][0] = f2_fma(aA.x, b0, acc[0][0]);
                acc[0][1] = f2_fma(aA.x, b1, acc[0][1]);
                acc[0][2] = f2_fma(aA.x, b2, acc[0][2]);
                acc[0][3] = f2_fma(aA.x, b3, acc[0][3]);
                acc[1][0] = f2_fma(aA.y, b0, acc[1][0]);
                acc[1][1] = f2_fma(aA.y, b1, acc[1][1]);
                acc[1][2] = f2_fma(aA.y, b2, acc[1][2]);
                acc[1][3] = f2_fma(aA.y, b3, acc[1][3]);
                acc[2][0] = f2_fma(aB.x, b0, acc[2][0]);
                acc[2][1] = f2_fma(aB.x, b1, acc[2][1]);
                acc[2][2] = f2_fma(aB.x, b2, acc[2][2]);
                acc[2][3] = f2_fma(aB.x, b3, acc[2][3]);
                acc[3][0] = f2_fma(aB.y, b0, acc[3][0]);
                acc[3][1] = f2_fma(aB.y, b1, acc[3][1]);
                acc[3][2] = f2_fma(aB.y, b2, acc[3][2]);
                acc[3][3] = f2_fma(aB.y, b3, acc[3][3]);
            }
        }
        const int cbase = ct * 128 + tc * 4;
        #pragma unroll
        for (int p = 0; p < 4; ++p) {
            #pragma unroll
            for (int j = 0; j < 4; ++j) {
                float lo, hi;
                f2_unpack(acc[p][j], lo, hi);
                if (lo > best[2 * p + 0]) { best[2 * p + 0] = lo; bidx[2 * p + 0] = cbase + j; }
                if (hi > best[2 * p + 1]) { best[2 * p + 1] = hi; bidx[2 * p + 1] = cbase + j; }
            }
        }
    }
    #pragma unroll
    for (int o = 1; o < 32; o <<= 1) {
        #pragma unroll
        for (int i = 0; i < 8; ++i) {
            float ov = __shfl_xor_sync(0xffffffffu, best[i], o);
            int   oi = __shfl_xor_sync(0xffffffffu, bidx[i], o);
            if (ov > best[i] || (ov == best[i] && oi < bidx[i])) { best[i] = ov; bidx[i] = oi; }
        }
    }
    if (tc == 0) {
        #pragma unroll
        for (int i = 0; i < 8; ++i) g_idx[row0 + tr * 8 + i] = bidx[i];
    }
}

// ---------------- gather z_q + commitment-loss partial ----------------
__global__ void k_zq(const float* __restrict__ emb) {
    __shared__ float red[256];
    const size_t N = (size_t)BATCH * DCH * T2;
    float local = 0.f;
    size_t base = (size_t)blockIdx.x * 256 + threadIdx.x;
    for (int k = 0; k < 8; ++k) {
        size_t lin = base + (size_t)k * 524288;
        if (lin < N) {
            int t = (int)(lin & 8191);
            int d = (int)((lin >> 13) & 127);
            int b = (int)(lin >> 20);
            int e = g_idx[b * T2 + t];
            float q  = emb[(size_t)e * DCH + d];
            float zz = g_z[lin];
            g_zq[lin] = q;
            float df = zz - q;
            local += df * df;
        }
    }
    red[threadIdx.x] = local;
    __syncthreads();
    for (int o = 128; o > 0; o >>= 1) {
        if (threadIdx.x < o) red[threadIdx.x] += red[threadIdx.x + o];
        __syncthreads();
    }
    if (threadIdx.x == 0) atomicAdd(&g_acc[1], (double)red[0]);
}

// ---------------- convT1 (FFMA2, smem-paired weights, 512 threads) ----------------
// thread = (co = tid&127, q = tid>>7); q selects p_local in [16q, 16q+16).
// out p gets exactly 2 taps: k=r from in[i_b], k=r+4 from in[i_b-1], r=(p+2)&3.
// Weights staged PRE-PAIRED over ci (even, odd) per 8-ci chunk; input pair-interleaved.
__global__ __launch_bounds__(512) void k_convT1(const float* __restrict__ w,
                                                const float* __restrict__ bias) {
    __shared__ float sp[64 * 40];     // input: 64 ci-pairs x 18 positions x 2, pad 40 (10KB)
    __shared__ ull   swp[32 * 129];   // 4 ci-pairs x 8 taps, [r][co] pre-paired (33KB)
    const int b  = blockIdx.y;
    const int p0 = blockIdx.x * 64;
    const int i0 = p0 / 4 - 1;
    for (int i = threadIdx.x; i < 128 * 18; i += 512) {
        int ci = i / 18, li = i % 18;
        int ii = i0 + li;
        float v = (ii >= 0 && ii < T2) ? g_h[((size_t)(b * DCH + ci)) * T2 + ii] : 0.f;
        sp[(ci >> 1) * 40 + li * 2 + (ci & 1)] = v;
    }
    const int co = threadIdx.x & 127;
    const int q  = threadIdx.x >> 7;
    ull acc2[16];
    #pragma unroll
    for (int t = 0; t < 16; ++t) acc2[t] = 0ull;

    for (int cc = 0; cc < 16; ++cc) {
        __syncthreads();   // prior chunk consumed (and input stores on first iter)
        // weights: swp[(m*8+k)*129 + co] = (w[cc*8+2m][co][k], w[cc*8+2m+1][co][k])
        for (int i = threadIdx.x; i < 4096; i += 512) {
            int j = i & 1023;          // co*8 + k
            int m = i >> 10;           // pair 0..3
            const float* wp = w + (size_t)(cc * 8 + 2 * m) * 1024 + j;
            swp[(m * 8 + (j & 7)) * 129 + (j >> 3)] = f2_pack(wp[0], wp[1024]);
        }
        __syncthreads();
        #pragma unroll
        for (int m = 0; m < 4; ++m) {
            const int pair = cc * 4 + m;
            ull pk[8];
            #pragma unroll
            for (int k = 0; k < 8; ++k) pk[k] = swp[(m * 8 + k) * 129 + co];
            const ulonglong2* rw = (const ulonglong2*)((const ull*)(sp + pair * 40) + 4 * q);
            ulonglong2 wA = rw[0], wB = rw[1], wC = rw[2];   // local positions 0..5
            ull pr[6] = {wA.x, wA.y, wB.x, wB.y, wC.x, wC.y};
            #pragma unroll
            for (int t = 0; t < 16; ++t) {
                const int r  = (t + 2) & 3;
                const int fb = ((t + 2) >> 2) + 1;
                acc2[t] = f2_fma(pr[fb - 1], pk[r + 4], acc2[t]);
                acc2[t] = f2_fma(pr[fb],     pk[r],     acc2[t]);
            }
        }
    }
    float* outp = g_buf1 + ((size_t)(b * DCH + co)) * T1 + p0 + 16 * q;
    float bv = bias[co];
    #pragma unroll
    for (int t = 0; t < 16; ++t) {
        float lo, hi;
        f2_unpack(acc2[t], lo, hi);
        outp[t] = gelu_exact(bv + lo + hi);
    }
}

// ---------------- convT2 + tanh + write xr + rec-loss partial ----------------
__global__ void k_convT2(const float* __restrict__ w, const float* __restrict__ bias,
                         const float* __restrict__ x, float* __restrict__ out) {
    __shared__ float s[128 * 68];
    __shared__ float sw[1024];
    __shared__ float red[256];
    const int b  = blockIdx.y;
    const int p0 = blockIdx.x * 256;
    const int i0 = p0 / 4 - 1;
    for (int i = threadIdx.x; i < 128 * 66; i += 256) {
        int ci = i / 66, li = i % 66;
        int ii = i0 + li;
        s[ci * 68 + li] = (ii >= 0 && ii < T1) ? g_buf1[((size_t)(b * DCH + ci)) * T1 + ii] : 0.f;
    }
    for (int i = threadIdx.x; i < 1024; i += 256) sw[i] = w[i];
    __syncthreads();
    const int p  = p0 + threadIdx.x;
    const int r  = (p + 2) & 3;
    const int ib = ((p + 2) >> 2) - i0;
    const int ia = ib - 1;
    float acc = bias[0];
    for (int ci = 0; ci < 128; ++ci) {
        acc += sw[ci * 8 + r + 4] * s[ci * 68 + ia] + sw[ci * 8 + r] * s[ci * 68 + ib];
    }
    float xr = tanhf(acc);
    out[XR_OFF + (size_t)b * TLEN + p] = xr;
    float df = xr - x[(size_t)b * TLEN + p];
    red[threadIdx.x] = df * df;
    __syncthreads();
    for (int o = 128; o > 0; o >>= 1) {
        if (threadIdx.x < o) red[threadIdx.x] += red[threadIdx.x + o];
        __syncthreads();
    }
    if (threadIdx.x == 0) atomicAdd(&g_acc[0], (double)red[0]);
}

// ---------------- write idx as float ----------------
__global__ void k_idxout(float* __restrict__ out) {
    int i = blockIdx.x * 256 + threadIdx.x;
    if (i < NROWS) out[IDX_OFF + i] = (float)g_idx[i];
}

// ---------------- finalize scalars: rec, com, ppx ----------------
__global__ void k_final(const float* __restrict__ cs, float* __restrict__ out) {
    __shared__ float red[256];
    __shared__ float s_total;
    float part = 0.f;
    for (int i = threadIdx.x; i < KCODE; i += 256) part += cs[i];
    red[threadIdx.x] = part;
    __syncthreads();
    for (int o = 128; o > 0; o >>= 1) {
        if (threadIdx.x < o) red[threadIdx.x] += red[threadIdx.x + o];
        __syncthreads();
    }
    if (threadIdx.x == 0) s_total = red[0];
    __syncthreads();
    float denom = s_total + 1e-6f;
    float ent = 0.f;
    for (int i = threadIdx.x; i < KCODE; i += 256) {
        float n = cs[i] / denom;
        ent += n * logf(n + 1e-6f);
    }
    red[threadIdx.x] = ent;
    __syncthreads();
    for (int o = 128; o > 0; o >>= 1) {
        if (threadIdx.x < o) red[threadIdx.x] += red[threadIdx.x + o];
        __syncthreads();
    }
    if (threadIdx.x == 0) {
        out[0] = (float)(g_acc[0] / (double)((size_t)BATCH * TLEN));
        out[1] = (float)(g_acc[1] / (double)((size_t)BATCH * DCH * T2));
        out[2] = expf(-red[0]);
    }
}

// ---------------- launch ----------------
extern "C" void kernel_launch(void* const* d_in, const int* in_sizes, int n_in,
                              void* d_out, int out_size) {
    const float* x      = (const float*)d_in[0];
    const float* enc_w1 = (const float*)d_in[1];
    const float* enc_b1 = (const float*)d_in[2];
    const float* enc_w2 = (const float*)d_in[3];
    const float* enc_b2 = (const float*)d_in[4];
    const float* enc_w3 = (const float*)d_in[5];
    const float* enc_b3 = (const float*)d_in[6];
    const float* dec_w0 = (const float*)d_in[7];
    const float* dec_b0 = (const float*)d_in[8];
    const float* dec_wt1= (const float*)d_in[9];
    const float* dec_bt1= (const float*)d_in[10];
    const float* dec_wt2= (const float*)d_in[11];
    const float* dec_bt2= (const float*)d_in[12];
    const float* emb    = (const float*)d_in[13];
    const float* cs     = (const float*)d_in[14];
    float* out = (float*)d_out;

    k_zero<<<1, 32>>>();
    k_conv1<<<dim3(T1 / 256, BATCH), 256>>>(x, enc_w1, enc_b1);
    k_conv2<<<dim3(T2 / 16, BATCH), 128>>>(enc_w2, enc_b2);
    k_conv3<0><<<dim3(T2 / 32, BATCH), 256>>>(enc_w3, enc_b3);
    k_embnorm<<<KCODE / 8, 256>>>(emb);
    k_vqgemm<<<NROWS / 64, 256>>>();
    k_zq<<<2048, 256>>>(emb);
    k_conv3<1><<<dim3(T2 / 32, BATCH), 256>>>(dec_w0, dec_b0);
    k_convT1<<<dim3(T1 / 64, BATCH), 512>>>(dec_wt1, dec_bt1);
    k_convT2<<<dim3(TLEN / 256, BATCH), 256>>>(dec_wt2, dec_bt2, x, out);
    k_idxout<<<NROWS / 256, 256>>>(out);
    k_final<<<1, 256>>>(cs, out);
}

// round 13
// speedup vs baseline: 1.0340x; 1.0340x over previous
#include <cuda_runtime.h>
#include <math.h>

// ---------------- problem constants ----------------
#define BATCH 4
#define TLEN  131072          // waveform length
#define T1    32768           // after conv1 (stride 4)
#define T2    8192            // after conv2 (stride 4)
#define DCH   128             // channels / code dim
#define KCODE 2048            // codebook size
#define NROWS (BATCH*T2)      // 32768 VQ rows

#define XR_OFF  3
#define IDX_OFF (3 + BATCH*TLEN)   // 3 + 524288

typedef unsigned long long ull;

// ---------------- scratch (device globals; no cudaMalloc allowed) ----------------
// NOTE: never pass these as kernel arguments from host code (host shadow symbol
// trap on ATS systems) — always reference them directly from device code.
__device__ float g_buf1[BATCH*DCH*T1];   // z1, later reused as decoder upsample-1 output
__device__ float g_z2 [BATCH*DCH*T2];
__device__ float g_z  [BATCH*DCH*T2];    // raw z, d-major (for commitment loss)
__device__ float g_znt[NROWS*DCH];       // normalized z, t-major [row][d]
__device__ float g_zq [BATCH*DCH*T2];
__device__ float g_h  [BATCH*DCH*T2];
__device__ float g_embnT[DCH*KCODE];     // normalized embedding, TRANSPOSED [d][e]
__device__ int   g_idx[NROWS];
__device__ double g_acc[2];              // [0]=rec sum, [1]=com sum

__device__ __forceinline__ float gelu_exact(float v) {
    return 0.5f * v * (1.0f + erff(v * 0.70710678118654752440f));
}

// ---------------- packed f32x2 helpers (Blackwell FFMA2) — GEMM use only ----------------
__device__ __forceinline__ ull f2_fma(ull a, ull b, ull c) {
    ull d;
    asm("fma.rn.f32x2 %0, %1, %2, %3;" : "=l"(d) : "l"(a), "l"(b), "l"(c));
    return d;
}
__device__ __forceinline__ ull f2_dup(float v) {
    ull d;
    asm("mov.b64 %0, {%1, %1};" : "=l"(d) : "f"(v));
    return d;
}
__device__ __forceinline__ void f2_unpack(ull p, float& lo, float& hi) {
    asm("mov.b64 {%0, %1}, %2;" : "=f"(lo), "=f"(hi) : "l"(p));
}

// ---------------- zero accumulators ----------------
__global__ void k_zero() {
    if (threadIdx.x < 2) g_acc[threadIdx.x] = 0.0;
}

// ---------------- conv1: [B,1,T] -> gelu -> [B,128,T1], k=8, s=4, p=2 ----------------
// Window sx[4t..4t+7] is invariant across the 128 output channels: hoist into
// registers once; inner loop = 2 broadcast LDS.128 + 8 FFMA + gelu + coalesced STG.
__global__ __launch_bounds__(256) void k_conv1(const float* __restrict__ x,
                                               const float* __restrict__ w,
                                               const float* __restrict__ bias) {
    __shared__ float sx[1032];
    __shared__ float sw[1024];
    __shared__ float sb[128];
    const int b  = blockIdx.y;
    const int t0 = blockIdx.x * 256;
    const int in0 = 4 * t0 - 2;
    for (int i = threadIdx.x; i < 1032; i += 256) {
        int p = in0 + i;
        sx[i] = (p >= 0 && p < TLEN) ? x[b * TLEN + p] : 0.f;
    }
    for (int i = threadIdx.x; i < 1024; i += 256) sw[i] = w[i];
    if (threadIdx.x < 128) sb[threadIdx.x] = bias[threadIdx.x];
    __syncthreads();
    const int t = threadIdx.x;
    float f[8];
    #pragma unroll
    for (int j = 0; j < 8; ++j) f[j] = sx[4 * t + j];
    float* outp = g_buf1 + ((size_t)b * DCH) * T1 + t0 + t;
    for (int c = 0; c < 128; ++c) {
        const float4 wa = *(const float4*)(sw + c * 8);
        const float4 wb = *(const float4*)(sw + c * 8 + 4);
        float a = sb[c] + wa.x * f[0] + wa.y * f[1] + wa.z * f[2] + wa.w * f[3]
                        + wb.x * f[4] + wb.y * f[5] + wb.z * f[6] + wb.w * f[7];
        outp[(size_t)c * T1] = gelu_exact(a);
    }
}

// ---------------- conv2 (scalar, R9): [B,128,T1] -> gelu -> [B,128,T2], k=8, s=4 -------
__global__ __launch_bounds__(128) void k_conv2(const float* __restrict__ w,
                                               const float* __restrict__ bias) {
    __shared__ float s[128 * 68];
    const int b  = blockIdx.y;
    const int t0 = blockIdx.x * 16;
    const int in0 = 4 * t0 - 2;
    for (int i = threadIdx.x; i < 128 * 68; i += 128) {
        int ci = i / 68, li = i % 68;
        int p = in0 + li;
        s[i] = (p >= 0 && p < T1) ? g_buf1[((size_t)(b * DCH + ci)) * T1 + p] : 0.f;
    }
    __syncthreads();
    const int c = threadIdx.x;
    float acc[16];
    {
        float bv = bias[c];
        #pragma unroll
        for (int t = 0; t < 16; ++t) acc[t] = bv;
    }
    for (int ci = 0; ci < 128; ++ci) {
        const float* wp = w + (size_t)(c * 128 + ci) * 8;
        const float4 wa = *(const float4*)wp;
        const float4 wb = *(const float4*)(wp + 4);
        const float4* row = (const float4*)(s + ci * 68);
        float4 v = row[0];
        #pragma unroll
        for (int t = 0; t < 16; ++t) {
            float4 vn = row[t + 1];
            acc[t] += wa.x * v.x + wa.y * v.y + wa.z * v.z + wa.w * v.w
                    + wb.x * vn.x + wb.y * vn.y + wb.z * vn.z + wb.w * vn.w;
            v = vn;
        }
    }
    float* outp = g_z2 + ((size_t)(b * DCH + c)) * T2 + t0;
    #pragma unroll
    for (int t = 0; t < 16; ++t) outp[t] = gelu_exact(acc[t]);
}

// ---------------- k3 conv (s=1, p=1), smem-staged weights, 256 threads ----------------
// STAGE 0: enc conv3, g_z2 -> g_z (raw, d-major) + g_znt (L2-normalized, t-major)
// STAGE 1: dec conv0, g_zq -> gelu -> g_h
template <int STAGE>
__global__ __launch_bounds__(256) void k_conv3(const float* __restrict__ w,
                                               const float* __restrict__ bias) {
    const float* __restrict__ in = (STAGE == 0) ? g_z2 : g_zq;
    __shared__ float s[128 * 36];      // input, span 34 padded to 36; reused for norm overlay
    __shared__ float swt[48 * 129];    // weight chunk: 16 ci x 3 taps, transposed [r][c]
    __shared__ float sinv[32];
    const int b  = blockIdx.y;
    const int t0 = blockIdx.x * 32;
    const int in0 = t0 - 1;
    for (int i = threadIdx.x; i < 128 * 34; i += 256) {
        int ci = i / 34, li = i % 34;
        int p = in0 + li;
        s[ci * 36 + li] = (p >= 0 && p < T2) ? in[((size_t)(b * DCH + ci)) * T2 + p] : 0.f;
    }
    const int c = threadIdx.x & 127;
    const int h = threadIdx.x >> 7;
    float acc[16];
    {
        float bv = bias[c];
        #pragma unroll
        for (int t = 0; t < 16; ++t) acc[t] = bv;
    }
    for (int cc = 0; cc < 8; ++cc) {
        __syncthreads();   // prior chunk reads done (and input stores on first iter)
        for (int i = threadIdx.x; i < 6144; i += 256) {
            int wc = i / 48, r = i - wc * 48;
            swt[r * 129 + wc] = w[wc * 384 + cc * 48 + r];
        }
        __syncthreads();
        #pragma unroll
        for (int cil = 0; cil < 16; ++cil) {
            const int ci = cc * 16 + cil;
            float w0 = swt[(cil * 3 + 0) * 129 + c];
            float w1 = swt[(cil * 3 + 1) * 129 + c];
            float w2 = swt[(cil * 3 + 2) * 129 + c];
            const float4* row4 = (const float4*)(s + ci * 36) + 4 * h;
            float f[20];
            #pragma unroll
            for (int q = 0; q < 5; ++q) {
                float4 v = row4[q];
                f[q * 4 + 0] = v.x; f[q * 4 + 1] = v.y; f[q * 4 + 2] = v.z; f[q * 4 + 3] = v.w;
            }
            #pragma unroll
            for (int t = 0; t < 16; ++t)
                acc[t] = fmaf(w0, f[t], fmaf(w1, f[t + 1], fmaf(w2, f[t + 2], acc[t])));
        }
    }
    if (STAGE == 1) {
        float* outp = g_h + ((size_t)(b * DCH + c)) * T2 + t0 + 16 * h;
        #pragma unroll
        for (int t = 0; t < 16; ++t) outp[t] = gelu_exact(acc[t]);
        return;
    }
    // STAGE 0: fused row normalization across channels (block owns all 128 c)
    __syncthreads();   // everyone done reading s
    #pragma unroll
    for (int t = 0; t < 16; ++t) s[(16 * h + t) * 132 + c] = acc[t] * acc[t];
    __syncthreads();
    if (threadIdx.x < 128) {
        const int t = threadIdx.x >> 2;
        const int q = threadIdx.x & 3;
        float sm = 0.f;
        #pragma unroll
        for (int j = 0; j < 32; ++j) sm += s[t * 132 + q * 32 + j];
        sm += __shfl_xor_sync(0xffffffffu, sm, 1);
        sm += __shfl_xor_sync(0xffffffffu, sm, 2);
        if (q == 0) sinv[t] = 1.0f / fmaxf(sqrtf(sm), 1e-12f);
    }
    __syncthreads();
    {
        float* outp = g_z + ((size_t)(b * DCH + c)) * T2 + t0 + 16 * h;
        #pragma unroll
        for (int t = 0; t < 16; ++t) {
            outp[t] = acc[t];
            g_znt[(size_t)(b * T2 + t0 + 16 * h + t) * DCH + c] = acc[t] * sinv[16 * h + t];
        }
    }
}

// ---------------- normalize embedding rows, store transposed [d][e] ----------------
__global__ void k_embnorm(const float* __restrict__ emb) {
    const int e    = blockIdx.x * 8 + (threadIdx.x >> 5);
    const int lane = threadIdx.x & 31;
    float4 v = *(const float4*)(emb + (size_t)e * DCH + lane * 4);
    float ss = v.x * v.x + v.y * v.y + v.z * v.z + v.w * v.w;
    #pragma unroll
    for (int o = 16; o > 0; o >>= 1) ss += __shfl_xor_sync(0xffffffffu, ss, o);
    float inv = 1.0f / fmaxf(sqrtf(ss), 1e-12f);
    g_embnT[(size_t)(lane * 4 + 0) * KCODE + e] = v.x * inv;
    g_embnT[(size_t)(lane * 4 + 1) * KCODE + e] = v.y * inv;
    g_embnT[(size_t)(lane * 4 + 2) * KCODE + e] = v.z * inv;
    g_embnT[(size_t)(lane * 4 + 3) * KCODE + e] = v.w * inv;
}

// ---------------- VQ GEMM + argmax, packed f32x2 (kept from R4 — proven win) ----------
__global__ __launch_bounds__(256) void k_vqgemm() {
    __shared__ float sA[128 * 64];   // [k][row] 32KB
    __shared__ float sB[16 * 128];   // [kk][c]   8KB
    const int tx   = threadIdx.x;
    const int row0 = blockIdx.x * 64;
    for (int it = tx; it < 2048; it += 256) {
        int row = it & 63, kq = it >> 6;
        float4 v = *(const float4*)&g_znt[(size_t)(row0 + row) * DCH + kq * 4];
        sA[(kq * 4 + 0) * 64 + row] = v.x;
        sA[(kq * 4 + 1) * 64 + row] = v.y;
        sA[(kq * 4 + 2) * 64 + row] = v.z;
        sA[(kq * 4 + 3) * 64 + row] = v.w;
    }
    const int tr = tx >> 5;
    const int tc = tx & 31;
    float best[8];
    int   bidx[8];
    #pragma unroll
    for (int i = 0; i < 8; ++i) { best[i] = -1e30f; bidx[i] = 0; }

    for (int ct = 0; ct < KCODE / 128; ++ct) {
        ull acc[4][4];
        #pragma unroll
        for (int p = 0; p < 4; ++p)
            #pragma unroll
            for (int j = 0; j < 4; ++j) acc[p][j] = 0ull;
        for (int kc = 0; kc < 8; ++kc) {
            __syncthreads();
            for (int it = tx; it < 512; it += 256) {
                int kk = it >> 5, c4 = it & 31;
                *(float4*)&sB[kk * 128 + c4 * 4] =
                    *(const float4*)&g_embnT[(size_t)(kc * 16 + kk) * KCODE + ct * 128 + c4 * 4];
            }
            __syncthreads();
            #pragma unroll 4
            for (int kk = 0; kk < 16; ++kk) {
                const int k = kc * 16 + kk;
                ulonglong2 aA = *(const ulonglong2*)&sA[k * 64 + tr * 8];
                ulonglong2 aB = *(const ulonglong2*)&sA[k * 64 + tr * 8 + 4];
                float4 bv = *(const float4*)&sB[kk * 128 + tc * 4];
                ull b0 = f2_dup(bv.x), b1 = f2_dup(bv.y);
                ull b2 = f2_dup(bv.z), b3 = f2_dup(bv.w);
                acc[0][0] = f2_fma(aA.x, b0, acc[0][0]);
                acc[0][1] = f2_fma(aA.x, b1, acc[0][1]);
                acc[0][2] = f2_fma(aA.x, b2, acc[0][2]);
                acc[0][3] = f2_fma(aA.x, b3, acc[0][3]);
                acc[1][0] = f2_fma(aA.y, b0, acc[1][0]);
                acc[1][1] = f2_fma(aA.y, b1, acc[1][1]);
                acc[1][2] = f2_fma(aA.y, b2, acc[1][2]);
                acc[1][3] = f2_fma(aA.y, b3, acc[1][3]);
                acc[2][0] = f2_fma(aB.x, b0, acc[2][0]);
                acc[2][1] = f2_fma(aB.x, b1, acc[2][1]);
                acc[2][2] = f2_fma(aB.x, b2, acc[2][2]);
                acc[2][3] = f2_fma(aB.x, b3, acc[2][3]);
                acc[3][0] = f2_fma(aB.y, b0, acc[3][0]);
                acc[3][1] = f2_fma(aB.y, b1, acc[3][1]);
                acc[3][2] = f2_fma(aB.y, b2, acc[3][2]);
                acc[3][3] = f2_fma(aB.y, b3, acc[3][3]);
            }
        }
        const int cbase = ct * 128 + tc * 4;
        #pragma unroll
        for (int p = 0; p < 4; ++p) {
            #pragma unroll
            for (int j = 0; j < 4; ++j) {
                float lo, hi;
                f2_unpack(acc[p][j], lo, hi);
                if (lo > best[2 * p + 0]) { best[2 * p + 0] = lo; bidx[2 * p + 0] = cbase + j; }
                if (hi > best[2 * p + 1]) { best[2 * p + 1] = hi; bidx[2 * p + 1] = cbase + j; }
            }
        }
    }
    #pragma unroll
    for (int o = 1; o < 32; o <<= 1) {
        #pragma unroll
        for (int i = 0; i < 8; ++i) {
            float ov = __shfl_xor_sync(0xffffffffu, best[i], o);
            int   oi = __shfl_xor_sync(0xffffffffu, bidx[i], o);
            if (ov > best[i] || (ov == best[i] && oi < bidx[i])) { best[i] = ov; bidx[i] = oi; }
        }
    }
    if (tc == 0) {
        #pragma unroll
        for (int i = 0; i < 8; ++i) g_idx[row0 + tr * 8 + i] = bidx[i];
    }
}

// ---------------- gather z_q + commitment-loss partial ----------------
__global__ void k_zq(const float* __restrict__ emb) {
    __shared__ float red[256];
    const size_t N = (size_t)BATCH * DCH * T2;
    float local = 0.f;
    size_t base = (size_t)blockIdx.x * 256 + threadIdx.x;
    for (int k = 0; k < 8; ++k) {
        size_t lin = base + (size_t)k * 524288;
        if (lin < N) {
            int t = (int)(lin & 8191);
            int d = (int)((lin >> 13) & 127);
            int b = (int)(lin >> 20);
            int e = g_idx[b * T2 + t];
            float q  = emb[(size_t)e * DCH + d];
            float zz = g_z[lin];
            g_zq[lin] = q;
            float df = zz - q;
            local += df * df;
        }
    }
    red[threadIdx.x] = local;
    __syncthreads();
    for (int o = 128; o > 0; o >>= 1) {
        if (threadIdx.x < o) red[threadIdx.x] += red[threadIdx.x + o];
        __syncthreads();
    }
    if (threadIdx.x == 0) atomicAdd(&g_acc[1], (double)red[0]);
}

// ---------------- convT1 (scalar 2-tap, R9, 512 threads) ----------------
// thread = (co = tid&127, q = tid>>7); q selects p_local in [16q, 16q+16).
// out p gets exactly 2 taps: k=r from in[i_b], k=r+4 from in[i_b-1], r=(p+2)&3.
__global__ __launch_bounds__(512) void k_convT1(const float* __restrict__ w,
                                                const float* __restrict__ bias) {
    __shared__ float s[128 * 20];   // 18 input positions per channel, padded to 20
    const int b  = blockIdx.y;
    const int p0 = blockIdx.x * 64;
    const int i0 = p0 / 4 - 1;
    for (int i = threadIdx.x; i < 128 * 18; i += 512) {
        int ci = i / 18, li = i % 18;
        int ii = i0 + li;
        s[ci * 20 + li] = (ii >= 0 && ii < T2) ? g_h[((size_t)(b * DCH + ci)) * T2 + ii] : 0.f;
    }
    __syncthreads();
    const int co = threadIdx.x & 127;
    const int q  = threadIdx.x >> 7;
    float acc[16];
    {
        float bv = bias[co];
        #pragma unroll
        for (int t = 0; t < 16; ++t) acc[t] = bv;
    }
    for (int ci = 0; ci < 128; ++ci) {
        const float* wp = w + (size_t)(ci * 128 + co) * 8;
        const float4 wa = *(const float4*)wp;
        const float4 wb = *(const float4*)(wp + 4);
        const float wv[8] = {wa.x, wa.y, wa.z, wa.w, wb.x, wb.y, wb.z, wb.w};
        const float4* rr = (const float4*)(s + ci * 20) + q;   // 80-byte row stride: 16B-aligned
        float4 fA = rr[0], fB = rr[1];
        const float f[8] = {fA.x, fA.y, fA.z, fA.w, fB.x, fB.y, fB.z, fB.w};
        #pragma unroll
        for (int t = 0; t < 16; ++t) {
            const int r  = (t + 2) & 3;
            const int fb = ((t + 2) >> 2) + 1;
            acc[t] = fmaf(wv[r + 4], f[fb - 1], fmaf(wv[r], f[fb], acc[t]));
        }
    }
    float* outp = g_buf1 + ((size_t)(b * DCH + co)) * T1 + p0 + 16 * q;
    #pragma unroll
    for (int t = 0; t < 16; ++t) outp[t] = gelu_exact(acc[t]);
}

// ---------------- convT2 + tanh + write xr + rec-loss partial ----------------
__global__ void k_convT2(const float* __restrict__ w, const float* __restrict__ bias,
                         const float* __restrict__ x, float* __restrict__ out) {
    __shared__ float s[128 * 68];
    __shared__ float sw[1024];
    __shared__ float red[256];
    const int b  = blockIdx.y;
    const int p0 = blockIdx.x * 256;
    const int i0 = p0 / 4 - 1;
    for (int i = threadIdx.x; i < 128 * 66; i += 256) {
        int ci = i / 66, li = i % 66;
        int ii = i0 + li;
        s[ci * 68 + li] = (ii >= 0 && ii < T1) ? g_buf1[((size_t)(b * DCH + ci)) * T1 + ii] : 0.f;
    }
    for (int i = threadIdx.x; i < 1024; i += 256) sw[i] = w[i];
    __syncthreads();
    const int p  = p0 + threadIdx.x;
    const int r  = (p + 2) & 3;
    const int ib = ((p + 2) >> 2) - i0;
    const int ia = ib - 1;
    float acc = bias[0];
    for (int ci = 0; ci < 128; ++ci) {
        acc += sw[ci * 8 + r + 4] * s[ci * 68 + ia] + sw[ci * 8 + r] * s[ci * 68 + ib];
    }
    float xr = tanhf(acc);
    out[XR_OFF + (size_t)b * TLEN + p] = xr;
    float df = xr - x[(size_t)b * TLEN + p];
    red[threadIdx.x] = df * df;
    __syncthreads();
    for (int o = 128; o > 0; o >>= 1) {
        if (threadIdx.x < o) red[threadIdx.x] += red[threadIdx.x + o];
        __syncthreads();
    }
    if (threadIdx.x == 0) atomicAdd(&g_acc[0], (double)red[0]);
}

// ---------------- write idx as float ----------------
__global__ void k_idxout(float* __restrict__ out) {
    int i = blockIdx.x * 256 + threadIdx.x;
    if (i < NROWS) out[IDX_OFF + i] = (float)g_idx[i];
}

// ---------------- finalize scalars: rec, com, ppx ----------------
__global__ void k_final(const float* __restrict__ cs, float* __restrict__ out) {
    __shared__ float red[256];
    __shared__ float s_total;
    float part = 0.f;
    for (int i = threadIdx.x; i < KCODE; i += 256) part += cs[i];
    red[threadIdx.x] = part;
    __syncthreads();
    for (int o = 128; o > 0; o >>= 1) {
        if (threadIdx.x < o) red[threadIdx.x] += red[threadIdx.x + o];
        __syncthreads();
    }
    if (threadIdx.x == 0) s_total = red[0];
    __syncthreads();
    float denom = s_total + 1e-6f;
    float ent = 0.f;
    for (int i = threadIdx.x; i < KCODE; i += 256) {
        float n = cs[i] / denom;
        ent += n * logf(n + 1e-6f);
    }
    red[threadIdx.x] = ent;
    __syncthreads();
    for (int o = 128; o > 0; o >>= 1) {
        if (threadIdx.x < o) red[threadIdx.x] += red[threadIdx.x + o];
        __syncthreads();
    }
    if (threadIdx.x == 0) {
        out[0] = (float)(g_acc[0] / (double)((size_t)BATCH * TLEN));
        out[1] = (float)(g_acc[1] / (double)((size_t)BATCH * DCH * T2));
        out[2] = expf(-red[0]);
    }
}

// ---------------- launch ----------------
extern "C" void kernel_launch(void* const* d_in, const int* in_sizes, int n_in,
                              void* d_out, int out_size) {
    const float* x      = (const float*)d_in[0];
    const float* enc_w1 = (const float*)d_in[1];
    const float* enc_b1 = (const float*)d_in[2];
    const float* enc_w2 = (const float*)d_in[3];
    const float* enc_b2 = (const float*)d_in[4];
    const float* enc_w3 = (const float*)d_in[5];
    const float* enc_b3 = (const float*)d_in[6];
    const float* dec_w0 = (const float*)d_in[7];
    const float* dec_b0 = (const float*)d_in[8];
    const float* dec_wt1= (const float*)d_in[9];
    const float* dec_bt1= (const float*)d_in[10];
    const float* dec_wt2= (const float*)d_in[11];
    const float* dec_bt2= (const float*)d_in[12];
    const float* emb    = (const float*)d_in[13];
    const float* cs     = (const float*)d_in[14];
    float* out = (float*)d_out;

    k_zero<<<1, 32>>>();
    k_conv1<<<dim3(T1 / 256, BATCH), 256>>>(x, enc_w1, enc_b1);
    k_conv2<<<dim3(T2 / 16, BATCH), 128>>>(enc_w2, enc_b2);
    k_conv3<0><<<dim3(T2 / 32, BATCH), 256>>>(enc_w3, enc_b3);
    k_embnorm<<<KCODE / 8, 256>>>(emb);
    k_vqgemm<<<NROWS / 64, 256>>>();
    k_zq<<<2048, 256>>>(emb);
    k_conv3<1><<<dim3(T2 / 32, BATCH), 256>>>(dec_w0, dec_b0);
    k_convT1<<<dim3(T1 / 64, BATCH), 512>>>(dec_wt1, dec_bt1);
    k_convT2<<<dim3(TLEN / 256, BATCH), 256>>>(dec_wt2, dec_bt2, x, out);
    k_idxout<<<NROWS / 256, 256>>>(out);
    k_final<<<1, 256>>>(cs, out);
}

// round 16
// speedup vs baseline: 1.2682x; 1.2265x over previous
#include <cuda_runtime.h>
#include <math.h>

// ---------------- problem constants ----------------
#define BATCH 4
#define TLEN  131072          // waveform length
#define T1    32768           // after conv1 (stride 4)
#define T2    8192            // after conv2 (stride 4)
#define DCH   128             // channels / code dim
#define KCODE 2048            // codebook size
#define NROWS (BATCH*T2)      // 32768 VQ rows

#define XR_OFF  3
#define IDX_OFF (3 + BATCH*TLEN)   // 3 + 524288

typedef unsigned long long ull;

// ---------------- scratch (device globals; no cudaMalloc allowed) ----------------
// NOTE: never pass these as kernel arguments from host code (host shadow symbol
// trap on ATS systems) — always reference them directly from device code.
__device__ float g_buf1[BATCH*DCH*T1];   // z1, later reused as decoder upsample-1 output
__device__ float g_z2 [BATCH*DCH*T2];
__device__ float g_z  [BATCH*DCH*T2];    // raw z, d-major (for commitment loss)
__device__ float g_znt[NROWS*DCH];       // normalized z, t-major [row][d]
__device__ float g_zq [BATCH*DCH*T2];
__device__ float g_h  [BATCH*DCH*T2];
__device__ float g_embnT[DCH*KCODE];     // normalized embedding, TRANSPOSED [d][e]
__device__ int   g_idx[NROWS];
__device__ double g_acc[2];              // [0]=rec sum, [1]=com sum
// pre-packed weights (built per launch by prep kernels)
__device__ ull   g_pw2 [512*128];        // conv2:  (w[c][2m][k], w[c][2m+1][k]) at [(m*8+k)*128+c]
__device__ ull   g_pwT [512*128];        // convT1: (w[2m][co][k], w[2m+1][co][k]) at [(m*8+k)*128+co]
__device__ float g_pw3a[384*128];        // enc conv3 transposed: [ci*3+r][c]
__device__ float g_pw3b[384*128];        // dec conv0 transposed: [ci*3+r][c]

__device__ __forceinline__ float gelu_exact(float v) {
    return 0.5f * v * (1.0f + erff(v * 0.70710678118654752440f));
}

// ---------------- packed f32x2 helpers (Blackwell FFMA2) ----------------
__device__ __forceinline__ ull f2_fma(ull a, ull b, ull c) {
    ull d;
    asm("fma.rn.f32x2 %0, %1, %2, %3;" : "=l"(d) : "l"(a), "l"(b), "l"(c));
    return d;
}
__device__ __forceinline__ ull f2_dup(float v) {
    ull d;
    asm("mov.b64 %0, {%1, %1};" : "=l"(d) : "f"(v));
    return d;
}
__device__ __forceinline__ ull f2_pack(float lo, float hi) {
    ull d;
    asm("mov.b64 %0, {%1, %2};" : "=l"(d) : "f"(lo), "f"(hi));
    return d;
}
__device__ __forceinline__ void f2_unpack(ull p, float& lo, float& hi) {
    asm("mov.b64 {%0, %1}, %2;" : "=f"(lo), "=f"(hi) : "l"(p));
}

// ---------------- zero accumulators ----------------
__global__ void k_zero() {
    if (threadIdx.x < 2) g_acc[threadIdx.x] = 0.0;
}

// ---------------- weight prep kernels (run once per launch, ~15us total) ----------------
__global__ void k_pack2(const float* __restrict__ w) {
    int idx = blockIdx.x * 256 + threadIdx.x;      // 65536
    int r = idx >> 7, c = idx & 127;
    int m = r >> 3, k = r & 7;
    g_pw2[idx] = f2_pack(w[(size_t)c * 1024 + (2 * m) * 8 + k],
                         w[(size_t)c * 1024 + (2 * m + 1) * 8 + k]);
}
__global__ void k_packT(const float* __restrict__ w) {
    int idx = blockIdx.x * 256 + threadIdx.x;      // 65536
    int r = idx >> 7, co = idx & 127;
    int m = r >> 3, k = r & 7;
    g_pwT[idx] = f2_pack(w[(size_t)(2 * m) * 1024 + co * 8 + k],
                         w[(size_t)(2 * m + 1) * 1024 + co * 8 + k]);
}
template <int STAGE>
__global__ void k_pack3(const float* __restrict__ w) {
    int idx = blockIdx.x * 256 + threadIdx.x;      // 49152
    int rr = idx >> 7, c = idx & 127;
    float* dst = (STAGE == 0) ? g_pw3a : g_pw3b;
    dst[idx] = w[(size_t)c * 384 + rr];
}

// ---------------- conv1: [B,1,T] -> gelu -> [B,128,T1], k=8, s=4, p=2 ----------------
__global__ __launch_bounds__(256) void k_conv1(const float* __restrict__ x,
                                               const float* __restrict__ w,
                                               const float* __restrict__ bias) {
    __shared__ float sx[1032];
    __shared__ float sw[1024];
    __shared__ float sb[128];
    const int b  = blockIdx.y;
    const int t0 = blockIdx.x * 256;
    const int in0 = 4 * t0 - 2;
    for (int i = threadIdx.x; i < 1032; i += 256) {
        int p = in0 + i;
        sx[i] = (p >= 0 && p < TLEN) ? x[b * TLEN + p] : 0.f;
    }
    for (int i = threadIdx.x; i < 1024; i += 256) sw[i] = w[i];
    if (threadIdx.x < 128) sb[threadIdx.x] = bias[threadIdx.x];
    __syncthreads();
    const int t = threadIdx.x;
    float f[8];
    #pragma unroll
    for (int j = 0; j < 8; ++j) f[j] = sx[4 * t + j];
    float* outp = g_buf1 + ((size_t)b * DCH) * T1 + t0 + t;
    for (int c = 0; c < 128; ++c) {
        const float4 wa = *(const float4*)(sw + c * 8);
        const float4 wb = *(const float4*)(sw + c * 8 + 4);
        float a = sb[c] + wa.x * f[0] + wa.y * f[1] + wa.z * f[2] + wa.w * f[3]
                        + wb.x * f[4] + wb.y * f[5] + wb.z * f[6] + wb.w * f[7];
        outp[(size_t)c * T1] = gelu_exact(a);
    }
}

// ---------------- conv2 (FFMA2, pre-paired global weights): -> gelu -> [B,128,T2] ------
// Audited R5/R6 pair algebra; weights now from g_pw2 (coalesced LDG.64, L2-hit),
// no staging, no packing movs, no extra syncs.
__global__ __launch_bounds__(128) void k_conv2(const float* __restrict__ bias) {
    __shared__ float s[64 * 136];     // 64 ci-pairs x 68 positions x 2 interleaved
    const int b  = blockIdx.y;
    const int t0 = blockIdx.x * 16;
    const int in0 = 4 * t0 - 2;
    for (int i = threadIdx.x; i < 128 * 68; i += 128) {
        int ci = i / 68, li = i % 68;
        int p = in0 + li;
        float v = (p >= 0 && p < T1) ? g_buf1[((size_t)(b * DCH + ci)) * T1 + p] : 0.f;
        s[(ci >> 1) * 136 + li * 2 + (ci & 1)] = v;
    }
    __syncthreads();
    const int c = threadIdx.x;
    ull acc2[16];
    #pragma unroll
    for (int t = 0; t < 16; ++t) acc2[t] = 0ull;

    for (int m = 0; m < 64; ++m) {
        ull pk[8];
        #pragma unroll
        for (int k = 0; k < 8; ++k) pk[k] = g_pw2[(m * 8 + k) * 128 + c];
        const ulonglong2* row2 = (const ulonglong2*)(s + m * 136);
        ulonglong2 pA = row2[0];     // positions 0,1
        ulonglong2 pB = row2[1];     // positions 2,3
        #pragma unroll
        for (int t = 0; t < 16; ++t) {
            ulonglong2 pC = row2[2 * t + 2];   // positions 4t+4, 4t+5
            ulonglong2 pD = row2[2 * t + 3];   // positions 4t+6, 4t+7
            acc2[t] = f2_fma(pA.x, pk[0], acc2[t]);
            acc2[t] = f2_fma(pA.y, pk[1], acc2[t]);
            acc2[t] = f2_fma(pB.x, pk[2], acc2[t]);
            acc2[t] = f2_fma(pB.y, pk[3], acc2[t]);
            acc2[t] = f2_fma(pC.x, pk[4], acc2[t]);
            acc2[t] = f2_fma(pC.y, pk[5], acc2[t]);
            acc2[t] = f2_fma(pD.x, pk[6], acc2[t]);
            acc2[t] = f2_fma(pD.y, pk[7], acc2[t]);
            pA = pC; pB = pD;
        }
    }
    float* outp = g_z2 + ((size_t)(b * DCH + c)) * T2 + t0;
    float bv = bias[c];
    #pragma unroll
    for (int t = 0; t < 16; ++t) {
        float lo, hi;
        f2_unpack(acc2[t], lo, hi);
        outp[t] = gelu_exact(bv + lo + hi);
    }
}

// ---------------- k3 conv (s=1, p=1), transposed global weights, 256 threads ----------
// STAGE 0: enc conv3, g_z2 -> g_z + g_znt (normalized t-major). STAGE 1: g_zq -> g_h.
// Weights read directly from g_pw3* at [(ci*3+r)*128+c]: lane-coalesced LDG, L2-hit.
template <int STAGE>
__global__ __launch_bounds__(256) void k_conv3(const float* __restrict__ bias) {
    const float* __restrict__ in = (STAGE == 0) ? g_z2 : g_zq;
    const float* __restrict__ pw = (STAGE == 0) ? g_pw3a : g_pw3b;
    __shared__ float s[128 * 36];    // input, span 34 padded to 36; reused for norm overlay
    __shared__ float sinv[32];
    const int b  = blockIdx.y;
    const int t0 = blockIdx.x * 32;
    const int in0 = t0 - 1;
    for (int i = threadIdx.x; i < 128 * 34; i += 256) {
        int ci = i / 34, li = i % 34;
        int p = in0 + li;
        s[ci * 36 + li] = (p >= 0 && p < T2) ? in[((size_t)(b * DCH + ci)) * T2 + p] : 0.f;
    }
    __syncthreads();
    const int c = threadIdx.x & 127;
    const int h = threadIdx.x >> 7;
    float acc[16];
    {
        float bv = bias[c];
        #pragma unroll
        for (int t = 0; t < 16; ++t) acc[t] = bv;
    }
    for (int ci = 0; ci < 128; ++ci) {
        float w0 = pw[(ci * 3 + 0) * 128 + c];
        float w1 = pw[(ci * 3 + 1) * 128 + c];
        float w2 = pw[(ci * 3 + 2) * 128 + c];
        const float4* row4 = (const float4*)(s + ci * 36) + 4 * h;
        float f[20];
        #pragma unroll
        for (int q = 0; q < 5; ++q) {
            float4 v = row4[q];
            f[q * 4 + 0] = v.x; f[q * 4 + 1] = v.y; f[q * 4 + 2] = v.z; f[q * 4 + 3] = v.w;
        }
        #pragma unroll
        for (int t = 0; t < 16; ++t)
            acc[t] = fmaf(w0, f[t], fmaf(w1, f[t + 1], fmaf(w2, f[t + 2], acc[t])));
    }
    if (STAGE == 1) {
        float* outp = g_h + ((size_t)(b * DCH + c)) * T2 + t0 + 16 * h;
        #pragma unroll
        for (int t = 0; t < 16; ++t) outp[t] = gelu_exact(acc[t]);
        return;
    }
    // STAGE 0: fused row normalization across channels (block owns all 128 c)
    __syncthreads();   // everyone done reading s
    #pragma unroll
    for (int t = 0; t < 16; ++t) s[(16 * h + t) * 132 + c] = acc[t] * acc[t];
    __syncthreads();
    if (threadIdx.x < 128) {
        const int t = threadIdx.x >> 2;
        const int q = threadIdx.x & 3;
        float sm = 0.f;
        #pragma unroll
        for (int j = 0; j < 32; ++j) sm += s[t * 132 + q * 32 + j];
        sm += __shfl_xor_sync(0xffffffffu, sm, 1);
        sm += __shfl_xor_sync(0xffffffffu, sm, 2);
        if (q == 0) sinv[t] = 1.0f / fmaxf(sqrtf(sm), 1e-12f);
    }
    __syncthreads();
    {
        float* outp = g_z + ((size_t)(b * DCH + c)) * T2 + t0 + 16 * h;
        #pragma unroll
        for (int t = 0; t < 16; ++t) {
            outp[t] = acc[t];
            g_znt[(size_t)(b * T2 + t0 + 16 * h + t) * DCH + c] = acc[t] * sinv[16 * h + t];
        }
    }
}

// ---------------- normalize embedding rows, store transposed [d][e] ----------------
__global__ void k_embnorm(const float* __restrict__ emb) {
    const int e    = blockIdx.x * 8 + (threadIdx.x >> 5);
    const int lane = threadIdx.x & 31;
    float4 v = *(const float4*)(emb + (size_t)e * DCH + lane * 4);
    float ss = v.x * v.x + v.y * v.y + v.z * v.z + v.w * v.w;
    #pragma unroll
    for (int o = 16; o > 0; o >>= 1) ss += __shfl_xor_sync(0xffffffffu, ss, o);
    float inv = 1.0f / fmaxf(sqrtf(ss), 1e-12f);
    g_embnT[(size_t)(lane * 4 + 0) * KCODE + e] = v.x * inv;
    g_embnT[(size_t)(lane * 4 + 1) * KCODE + e] = v.y * inv;
    g_embnT[(size_t)(lane * 4 + 2) * KCODE + e] = v.z * inv;
    g_embnT[(size_t)(lane * 4 + 3) * KCODE + e] = v.w * inv;
}

// ---------------- VQ GEMM + argmax, packed f32x2 (R4 — proven) ----------
__global__ __launch_bounds__(256) void k_vqgemm() {
    __shared__ float sA[128 * 64];   // [k][row] 32KB
    __shared__ float sB[16 * 128];   // [kk][c]   8KB
    const int tx   = threadIdx.x;
    const int row0 = blockIdx.x * 64;
    for (int it = tx; it < 2048; it += 256) {
        int row = it & 63, kq = it >> 6;
        float4 v = *(const float4*)&g_znt[(size_t)(row0 + row) * DCH + kq * 4];
        sA[(kq * 4 + 0) * 64 + row] = v.x;
        sA[(kq * 4 + 1) * 64 + row] = v.y;
        sA[(kq * 4 + 2) * 64 + row] = v.z;
        sA[(kq * 4 + 3) * 64 + row] = v.w;
    }
    const int tr = tx >> 5;
    const int tc = tx & 31;
    float best[8];
    int   bidx[8];
    #pragma unroll
    for (int i = 0; i < 8; ++i) { best[i] = -1e30f; bidx[i] = 0; }

    for (int ct = 0; ct < KCODE / 128; ++ct) {
        ull acc[4][4];
        #pragma unroll
        for (int p = 0; p < 4; ++p)
            #pragma unroll
            for (int j = 0; j < 4; ++j) acc[p][j] = 0ull;
        for (int kc = 0; kc < 8; ++kc) {
            __syncthreads();
            for (int it = tx; it < 512; it += 256) {
                int kk = it >> 5, c4 = it & 31;
                *(float4*)&sB[kk * 128 + c4 * 4] =
                    *(const float4*)&g_embnT[(size_t)(kc * 16 + kk) * KCODE + ct * 128 + c4 * 4];
            }
            __syncthreads();
            #pragma unroll 4
            for (int kk = 0; kk < 16; ++kk) {
                const int k = kc * 16 + kk;
                ulonglong2 aA = *(const ulonglong2*)&sA[k * 64 + tr * 8];
                ulonglong2 aB = *(const ulonglong2*)&sA[k * 64 + tr * 8 + 4];
                float4 bv = *(const float4*)&sB[kk * 128 + tc * 4];
                ull b0 = f2_dup(bv.x), b1 = f2_dup(bv.y);
                ull b2 = f2_dup(bv.z), b3 = f2_dup(bv.w);
                acc[0][0] = f2_fma(aA.x, b0, acc[0][0]);
                acc[0][1] = f2_fma(aA.x, b1, acc[0][1]);
                acc[0][2] = f2_fma(aA.x, b2, acc[0][2]);
                acc[0][3] = f2_fma(aA.x, b3, acc[0][3]);
                acc[1][0] = f2_fma(aA.y, b0, acc[1][0]);
                acc[1][1] = f2_fma(aA.y, b1, acc[1][1]);
                acc[1][2] = f2_fma(aA.y, b2, acc[1][2]);
                acc[1][3] = f2_fma(aA.y, b3, acc[1][3]);
                acc[2][0] = f2_fma(aB.x, b0, acc[2][0]);
                acc[2][1] = f2_fma(aB.x, b1, acc[2][1]);
                acc[2][2] = f2_fma(aB.x, b2, acc[2][2]);
                acc[2][3] = f2_fma(aB.x, b3, acc[2][3]);
                acc[3][0] = f2_fma(aB.y, b0, acc[3][0]);
                acc[3][1] = f2_fma(aB.y, b1, acc[3][1]);
                acc[3][2] = f2_fma(aB.y, b2, acc[3][2]);
                acc[3][3] = f2_fma(aB.y, b3, acc[3][3]);
            }
        }
        const int cbase = ct * 128 + tc * 4;
        #pragma unroll
        for (int p = 0; p < 4; ++p) {
            #pragma unroll
            for (int j = 0; j < 4; ++j) {
                float lo, hi;
                f2_unpack(acc[p][j], lo, hi);
                if (lo > best[2 * p + 0]) { best[2 * p + 0] = lo; bidx[2 * p + 0] = cbase + j; }
                if (hi > best[2 * p + 1]) { best[2 * p + 1] = hi; bidx[2 * p + 1] = cbase + j; }
            }
        }
    }
    #pragma unroll
    for (int o = 1; o < 32; o <<= 1) {
        #pragma unroll
        for (int i = 0; i < 8; ++i) {
            float ov = __shfl_xor_sync(0xffffffffu, best[i], o);
            int   oi = __shfl_xor_sync(0xffffffffu, bidx[i], o);
            if (ov > best[i] || (ov == best[i] && oi < bidx[i])) { best[i] = ov; bidx[i] = oi; }
        }
    }
    if (tc == 0) {
        #pragma unroll
        for (int i = 0; i < 8; ++i) g_idx[row0 + tr * 8 + i] = bidx[i];
    }
}

// ---------------- gather z_q + commitment-loss partial ----------------
__global__ void k_zq(const float* __restrict__ emb) {
    __shared__ float red[256];
    const size_t N = (size_t)BATCH * DCH * T2;
    float local = 0.f;
    size_t base = (size_t)blockIdx.x * 256 + threadIdx.x;
    for (int k = 0; k < 8; ++k) {
        size_t lin = base + (size_t)k * 524288;
        if (lin < N) {
            int t = (int)(lin & 8191);
            int d = (int)((lin >> 13) & 127);
            int b = (int)(lin >> 20);
            int e = g_idx[b * T2 + t];
            float q  = emb[(size_t)e * DCH + d];
            float zz = g_z[lin];
            g_zq[lin] = q;
            float df = zz - q;
            local += df * df;
        }
    }
    red[threadIdx.x] = local;
    __syncthreads();
    for (int o = 128; o > 0; o >>= 1) {
        if (threadIdx.x < o) red[threadIdx.x] += red[threadIdx.x + o];
        __syncthreads();
    }
    if (threadIdx.x == 0) atomicAdd(&g_acc[1], (double)red[0]);
}

// ---------------- convT1 (FFMA2, pre-paired global weights, 512 threads) ----------------
// Audited R5 pair algebra; weights from g_pwT (coalesced LDG.64, L2-hit), no staging.
__global__ __launch_bounds__(512) void k_convT1(const float* __restrict__ bias) {
    __shared__ float sp[64 * 40];   // 64 ci-pairs x 18 positions x 2, row padded to 40
    const int b  = blockIdx.y;
    const int p0 = blockIdx.x * 64;
    const int i0 = p0 / 4 - 1;
    for (int i = threadIdx.x; i < 128 * 18; i += 512) {
        int ci = i / 18, li = i % 18;
        int ii = i0 + li;
        float v = (ii >= 0 && ii < T2) ? g_h[((size_t)(b * DCH + ci)) * T2 + ii] : 0.f;
        sp[(ci >> 1) * 40 + li * 2 + (ci & 1)] = v;
    }
    __syncthreads();
    const int co = threadIdx.x & 127;
    const int q  = threadIdx.x >> 7;
    ull acc2[16];
    #pragma unroll
    for (int t = 0; t < 16; ++t) acc2[t] = 0ull;

    for (int m = 0; m < 64; ++m) {
        ull pk[8];
        #pragma unroll
        for (int k = 0; k < 8; ++k) pk[k] = g_pwT[(m * 8 + k) * 128 + co];
        const ulonglong2* rw = (const ulonglong2*)((const ull*)(sp + m * 40) + 4 * q);
        ulonglong2 wA = rw[0], wB = rw[1], wC = rw[2];   // local positions 0..5
        ull pr[6] = {wA.x, wA.y, wB.x, wB.y, wC.x, wC.y};
        #pragma unroll
        for (int t = 0; t < 16; ++t) {
            const int r  = (t + 2) & 3;
            const int fb = ((t + 2) >> 2) + 1;
            acc2[t] = f2_fma(pr[fb - 1], pk[r + 4], acc2[t]);
            acc2[t] = f2_fma(pr[fb],     pk[r],     acc2[t]);
        }
    }
    float* outp = g_buf1 + ((size_t)(b * DCH + co)) * T1 + p0 + 16 * q;
    float bv = bias[co];
    #pragma unroll
    for (int t = 0; t < 16; ++t) {
        float lo, hi;
        f2_unpack(acc2[t], lo, hi);
        outp[t] = gelu_exact(bv + lo + hi);
    }
}

// ---------------- convT2 + tanh + write xr + rec-loss partial ----------------
__global__ void k_convT2(const float* __restrict__ w, const float* __restrict__ bias,
                         const float* __restrict__ x, float* __restrict__ out) {
    __shared__ float s[128 * 68];
    __shared__ float sw[1024];
    __shared__ float red[256];
    const int b  = blockIdx.y;
    const int p0 = blockIdx.x * 256;
    const int i0 = p0 / 4 - 1;
    for (int i = threadIdx.x; i < 128 * 66; i += 256) {
        int ci = i / 66, li = i % 66;
        int ii = i0 + li;
        s[ci * 68 + li] = (ii >= 0 && ii < T1) ? g_buf1[((size_t)(b * DCH + ci)) * T1 + ii] : 0.f;
    }
    for (int i = threadIdx.x; i < 1024; i += 256) sw[i] = w[i];
    __syncthreads();
    const int p  = p0 + threadIdx.x;
    const int r  = (p + 2) & 3;
    const int ib = ((p + 2) >> 2) - i0;
    const int ia = ib - 1;
    float acc = bias[0];
    for (int ci = 0; ci < 128; ++ci) {
        acc += sw[ci * 8 + r + 4] * s[ci * 68 + ia] + sw[ci * 8 + r] * s[ci * 68 + ib];
    }
    float xr = tanhf(acc);
    out[XR_OFF + (size_t)b * TLEN + p] = xr;
    float df = xr - x[(size_t)b * TLEN + p];
    red[threadIdx.x] = df * df;
    __syncthreads();
    for (int o = 128; o > 0; o >>= 1) {
        if (threadIdx.x < o) red[threadIdx.x] += red[threadIdx.x + o];
        __syncthreads();
    }
    if (threadIdx.x == 0) atomicAdd(&g_acc[0], (double)red[0]);
}

// ---------------- write idx as float ----------------
__global__ void k_idxout(float* __restrict__ out) {
    int i = blockIdx.x * 256 + threadIdx.x;
    if (i < NROWS) out[IDX_OFF + i] = (float)g_idx[i];
}

// ---------------- finalize scalars: rec, com, ppx ----------------
__global__ void k_final(const float* __restrict__ cs, float* __restrict__ out) {
    __shared__ float red[256];
    __shared__ float s_total;
    float part = 0.f;
    for (int i = threadIdx.x; i < KCODE; i += 256) part += cs[i];
    red[threadIdx.x] = part;
    __syncthreads();
    for (int o = 128; o > 0; o >>= 1) {
        if (threadIdx.x < o) red[threadIdx.x] += red[threadIdx.x + o];
        __syncthreads();
    }
    if (threadIdx.x == 0) s_total = red[0];
    __syncthreads();
    float denom = s_total + 1e-6f;
    float ent = 0.f;
    for (int i = threadIdx.x; i < KCODE; i += 256) {
        float n = cs[i] / denom;
        ent += n * logf(n + 1e-6f);
    }
    red[threadIdx.x] = ent;
    __syncthreads();
    for (int o = 128; o > 0; o >>= 1) {
        if (threadIdx.x < o) red[threadIdx.x] += red[threadIdx.x + o];
        __syncthreads();
    }
    if (threadIdx.x == 0) {
        out[0] = (float)(g_acc[0] / (double)((size_t)BATCH * TLEN));
        out[1] = (float)(g_acc[1] / (double)((size_t)BATCH * DCH * T2));
        out[2] = expf(-red[0]);
    }
}

// ---------------- launch ----------------
extern "C" void kernel_launch(void* const* d_in, const int* in_sizes, int n_in,
                              void* d_out, int out_size) {
    const float* x      = (const float*)d_in[0];
    const float* enc_w1 = (const float*)d_in[1];
    const float* enc_b1 = (const float*)d_in[2];
    const float* enc_w2 = (const float*)d_in[3];
    const float* enc_b2 = (const float*)d_in[4];
    const float* enc_w3 = (const float*)d_in[5];
    const float* enc_b3 = (const float*)d_in[6];
    const float* dec_w0 = (const float*)d_in[7];
    const float* dec_b0 = (const float*)d_in[8];
    const float* dec_wt1= (const float*)d_in[9];
    const float* dec_bt1= (const float*)d_in[10];
    const float* dec_wt2= (const float*)d_in[11];
    const float* dec_bt2= (const float*)d_in[12];
    const float* emb    = (const float*)d_in[13];
    const float* cs     = (const float*)d_in[14];
    float* out = (float*)d_out;

    k_zero<<<1, 32>>>();
    k_pack2<<<256, 256>>>(enc_w2);
    k_packT<<<256, 256>>>(dec_wt1);
    k_pack3<0><<<192, 256>>>(enc_w3);
    k_pack3<1><<<192, 256>>>(dec_w0);
    k_conv1<<<dim3(T1 / 256, BATCH), 256>>>(x, enc_w1, enc_b1);
    k_conv2<<<dim3(T2 / 16, BATCH), 128>>>(enc_b2);
    k_conv3<0><<<dim3(T2 / 32, BATCH), 256>>>(enc_b3);
    k_embnorm<<<KCODE / 8, 256>>>(emb);
    k_vqgemm<<<NROWS / 64, 256>>>();
    k_zq<<<2048, 256>>>(emb);
    k_conv3<1><<<dim3(T2 / 32, BATCH), 256>>>(dec_b0);
    k_convT1<<<dim3(T1 / 64, BATCH), 512>>>(dec_bt1);
    k_convT2<<<dim3(TLEN / 256, BATCH), 256>>>(dec_wt2, dec_bt2, x, out);
    k_idxout<<<NROWS / 256, 256>>>(out);
    k_final<<<1, 256>>>(cs, out);
}

// round 17
// speedup vs baseline: 1.2799x; 1.0092x over previous
#include <cuda_runtime.h>
#include <math.h>

// ---------------- problem constants ----------------
#define BATCH 4
#define TLEN  131072          // waveform length
#define T1    32768           // after conv1 (stride 4)
#define T2    8192            // after conv2 (stride 4)
#define DCH   128             // channels / code dim
#define KCODE 2048            // codebook size
#define NROWS (BATCH*T2)      // 32768 VQ rows

#define XR_OFF  3
#define IDX_OFF (3 + BATCH*TLEN)   // 3 + 524288

typedef unsigned long long ull;

// ---------------- scratch (device globals; no cudaMalloc allowed) ----------------
// NOTE: never pass these as kernel arguments from host code (host shadow symbol
// trap on ATS systems) — always reference them directly from device code.
__device__ float g_buf1[BATCH*DCH*T1];   // z1, later reused as decoder upsample-1 output
__device__ float g_z2 [BATCH*DCH*T2];
__device__ float g_z  [BATCH*DCH*T2];    // raw z, d-major (for commitment loss)
__device__ float g_znt[NROWS*DCH];       // normalized z, t-major [row][d]
__device__ float g_zq [BATCH*DCH*T2];
__device__ float g_h  [BATCH*DCH*T2];
__device__ float g_embnT[DCH*KCODE];     // normalized embedding, TRANSPOSED [d][e]
__device__ int   g_idx[NROWS];
__device__ double g_acc[2];              // [0]=rec sum, [1]=com sum
// pre-packed weights (built per launch by prep kernels)
__device__ ull   g_pw2 [512*128];        // conv2:  (w[c][2m][k], w[c][2m+1][k]) at [(m*8+k)*128+c]
__device__ ull   g_pwT [512*128];        // convT1: (w[2m][co][k], w[2m+1][co][k]) at [(m*8+k)*128+co]
__device__ ull   g_pw3pa[192*128];       // enc conv3: (w[c][2m][r], w[c][2m+1][r]) at [(m*3+r)*128+c]
__device__ ull   g_pw3pb[192*128];       // dec conv0: same layout

__device__ __forceinline__ float gelu_exact(float v) {
    return 0.5f * v * (1.0f + erff(v * 0.70710678118654752440f));
}

// ---------------- packed f32x2 helpers (Blackwell FFMA2) ----------------
__device__ __forceinline__ ull f2_fma(ull a, ull b, ull c) {
    ull d;
    asm("fma.rn.f32x2 %0, %1, %2, %3;" : "=l"(d) : "l"(a), "l"(b), "l"(c));
    return d;
}
__device__ __forceinline__ ull f2_dup(float v) {
    ull d;
    asm("mov.b64 %0, {%1, %1};" : "=l"(d) : "f"(v));
    return d;
}
__device__ __forceinline__ ull f2_pack(float lo, float hi) {
    ull d;
    asm("mov.b64 %0, {%1, %2};" : "=l"(d) : "f"(lo), "f"(hi));
    return d;
}
__device__ __forceinline__ void f2_unpack(ull p, float& lo, float& hi) {
    asm("mov.b64 {%0, %1}, %2;" : "=f"(lo), "=f"(hi) : "l"(p));
}

// ---------------- zero accumulators ----------------
__global__ void k_zero() {
    if (threadIdx.x < 2) g_acc[threadIdx.x] = 0.0;
}

// ---------------- weight prep kernels (run once per launch, ~15us total) ----------------
__global__ void k_pack2(const float* __restrict__ w) {
    int idx = blockIdx.x * 256 + threadIdx.x;      // 65536
    int r = idx >> 7, c = idx & 127;
    int m = r >> 3, k = r & 7;
    g_pw2[idx] = f2_pack(w[(size_t)c * 1024 + (2 * m) * 8 + k],
                         w[(size_t)c * 1024 + (2 * m + 1) * 8 + k]);
}
__global__ void k_packT(const float* __restrict__ w) {
    int idx = blockIdx.x * 256 + threadIdx.x;      // 65536
    int r = idx >> 7, co = idx & 127;
    int m = r >> 3, k = r & 7;
    g_pwT[idx] = f2_pack(w[(size_t)(2 * m) * 1024 + co * 8 + k],
                         w[(size_t)(2 * m + 1) * 1024 + co * 8 + k]);
}
// conv3 pairs: rr = m*3+r; (w[c][2m][r], w[c][2m+1][r]) = (w[c*384+6m+r], w[c*384+6m+3+r])
template <int STAGE>
__global__ void k_pack3(const float* __restrict__ w) {
    int idx = blockIdx.x * 256 + threadIdx.x;      // 24576
    int rr = idx >> 7, c = idx & 127;
    int m = rr / 3, r = rr - m * 3;
    ull* dst = (STAGE == 0) ? g_pw3pa : g_pw3pb;
    dst[idx] = f2_pack(w[(size_t)c * 384 + 6 * m + r],
                       w[(size_t)c * 384 + 6 * m + 3 + r]);
}

// ---------------- conv1: [B,1,T] -> gelu -> [B,128,T1], k=8, s=4, p=2 ----------------
__global__ __launch_bounds__(256) void k_conv1(const float* __restrict__ x,
                                               const float* __restrict__ w,
                                               const float* __restrict__ bias) {
    __shared__ float sx[1032];
    __shared__ float sw[1024];
    __shared__ float sb[128];
    const int b  = blockIdx.y;
    const int t0 = blockIdx.x * 256;
    const int in0 = 4 * t0 - 2;
    for (int i = threadIdx.x; i < 1032; i += 256) {
        int p = in0 + i;
        sx[i] = (p >= 0 && p < TLEN) ? x[b * TLEN + p] : 0.f;
    }
    for (int i = threadIdx.x; i < 1024; i += 256) sw[i] = w[i];
    if (threadIdx.x < 128) sb[threadIdx.x] = bias[threadIdx.x];
    __syncthreads();
    const int t = threadIdx.x;
    float f[8];
    #pragma unroll
    for (int j = 0; j < 8; ++j) f[j] = sx[4 * t + j];
    float* outp = g_buf1 + ((size_t)b * DCH) * T1 + t0 + t;
    for (int c = 0; c < 128; ++c) {
        const float4 wa = *(const float4*)(sw + c * 8);
        const float4 wb = *(const float4*)(sw + c * 8 + 4);
        float a = sb[c] + wa.x * f[0] + wa.y * f[1] + wa.z * f[2] + wa.w * f[3]
                        + wb.x * f[4] + wb.y * f[5] + wb.z * f[6] + wb.w * f[7];
        outp[(size_t)c * T1] = gelu_exact(a);
    }
}

// ---------------- conv2 (FFMA2, pre-paired global weights): -> gelu -> [B,128,T2] ------
__global__ __launch_bounds__(128) void k_conv2(const float* __restrict__ bias) {
    __shared__ float s[64 * 136];     // 64 ci-pairs x 68 positions x 2 interleaved
    const int b  = blockIdx.y;
    const int t0 = blockIdx.x * 16;
    const int in0 = 4 * t0 - 2;
    for (int i = threadIdx.x; i < 128 * 68; i += 128) {
        int ci = i / 68, li = i % 68;
        int p = in0 + li;
        float v = (p >= 0 && p < T1) ? g_buf1[((size_t)(b * DCH + ci)) * T1 + p] : 0.f;
        s[(ci >> 1) * 136 + li * 2 + (ci & 1)] = v;
    }
    __syncthreads();
    const int c = threadIdx.x;
    ull acc2[16];
    #pragma unroll
    for (int t = 0; t < 16; ++t) acc2[t] = 0ull;

    for (int m = 0; m < 64; ++m) {
        ull pk[8];
        #pragma unroll
        for (int k = 0; k < 8; ++k) pk[k] = g_pw2[(m * 8 + k) * 128 + c];
        const ulonglong2* row2 = (const ulonglong2*)(s + m * 136);
        ulonglong2 pA = row2[0];
        ulonglong2 pB = row2[1];
        #pragma unroll
        for (int t = 0; t < 16; ++t) {
            ulonglong2 pC = row2[2 * t + 2];
            ulonglong2 pD = row2[2 * t + 3];
            acc2[t] = f2_fma(pA.x, pk[0], acc2[t]);
            acc2[t] = f2_fma(pA.y, pk[1], acc2[t]);
            acc2[t] = f2_fma(pB.x, pk[2], acc2[t]);
            acc2[t] = f2_fma(pB.y, pk[3], acc2[t]);
            acc2[t] = f2_fma(pC.x, pk[4], acc2[t]);
            acc2[t] = f2_fma(pC.y, pk[5], acc2[t]);
            acc2[t] = f2_fma(pD.x, pk[6], acc2[t]);
            acc2[t] = f2_fma(pD.y, pk[7], acc2[t]);
            pA = pC; pB = pD;
        }
    }
    float* outp = g_z2 + ((size_t)(b * DCH + c)) * T2 + t0;
    float bv = bias[c];
    #pragma unroll
    for (int t = 0; t < 16; ++t) {
        float lo, hi;
        f2_unpack(acc2[t], lo, hi);
        outp[t] = gelu_exact(bv + lo + hi);
    }
}

// ---------------- k3 conv (s=1, p=1), FFMA2 + pre-paired global weights, 256 thr ------
// STAGE 0: enc conv3, g_z2 -> g_z + g_znt (normalized t-major). STAGE 1: g_zq -> g_h.
// Pair algebra execution-verified in R6; weights now lane-coalesced LDG.64 from g_pw3p*.
// thread = (c = tid&127, h = tid>>7); h selects t in [16h, 16h+16).
template <int STAGE>
__global__ __launch_bounds__(256) void k_conv3(const float* __restrict__ bias) {
    const float* __restrict__ in  = (STAGE == 0) ? g_z2 : g_zq;
    const ull*   __restrict__ pwp = (STAGE == 0) ? g_pw3pa : g_pw3pb;
    __shared__ float s2[64 * 72];    // 64 ci-pairs x 34 positions x 2, row pad 72 (18KB)
    __shared__ float sinv[32];
    const int b  = blockIdx.y;
    const int t0 = blockIdx.x * 32;
    const int in0 = t0 - 1;
    for (int i = threadIdx.x; i < 128 * 34; i += 256) {
        int ci = i / 34, li = i % 34;
        int p = in0 + li;
        float v = (p >= 0 && p < T2) ? in[((size_t)(b * DCH + ci)) * T2 + p] : 0.f;
        s2[(ci >> 1) * 72 + li * 2 + (ci & 1)] = v;
    }
    __syncthreads();
    const int c = threadIdx.x & 127;
    const int h = threadIdx.x >> 7;
    ull acc2[16];
    #pragma unroll
    for (int t = 0; t < 16; ++t) acc2[t] = 0ull;

    for (int m = 0; m < 64; ++m) {
        ull pk0 = pwp[(m * 3 + 0) * 128 + c];
        ull pk1 = pwp[(m * 3 + 1) * 128 + c];
        ull pk2 = pwp[(m * 3 + 2) * 128 + c];
        const ulonglong2* r2 = (const ulonglong2*)((const ull*)(s2 + m * 72) + 16 * h);
        ulonglong2 pA = r2[0];   // local position pairs 0,1
        #pragma unroll
        for (int u = 0; u < 8; ++u) {
            ulonglong2 pB = r2[u + 1];   // local position pairs 2u+2, 2u+3
            acc2[2 * u]     = f2_fma(pA.x, pk0, acc2[2 * u]);
            acc2[2 * u]     = f2_fma(pA.y, pk1, acc2[2 * u]);
            acc2[2 * u]     = f2_fma(pB.x, pk2, acc2[2 * u]);
            acc2[2 * u + 1] = f2_fma(pA.y, pk0, acc2[2 * u + 1]);
            acc2[2 * u + 1] = f2_fma(pB.x, pk1, acc2[2 * u + 1]);
            acc2[2 * u + 1] = f2_fma(pB.y, pk2, acc2[2 * u + 1]);
            pA = pB;
        }
    }
    float vals[16];
    {
        float bv = bias[c];
        #pragma unroll
        for (int t = 0; t < 16; ++t) {
            float lo, hi;
            f2_unpack(acc2[t], lo, hi);
            vals[t] = bv + lo + hi;
        }
    }
    if (STAGE == 1) {
        float* outp = g_h + ((size_t)(b * DCH + c)) * T2 + t0 + 16 * h;
        #pragma unroll
        for (int t = 0; t < 16; ++t) outp[t] = gelu_exact(vals[t]);
        return;
    }
    // STAGE 0: fused row normalization across channels (block owns all 128 c)
    __syncthreads();   // everyone done reading s2
    #pragma unroll
    for (int t = 0; t < 16; ++t) s2[(16 * h + t) * 132 + c] = vals[t] * vals[t];
    __syncthreads();
    if (threadIdx.x < 128) {
        const int t = threadIdx.x >> 2;
        const int q = threadIdx.x & 3;
        float sm = 0.f;
        #pragma unroll
        for (int j = 0; j < 32; ++j) sm += s2[t * 132 + q * 32 + j];
        sm += __shfl_xor_sync(0xffffffffu, sm, 1);
        sm += __shfl_xor_sync(0xffffffffu, sm, 2);
        if (q == 0) sinv[t] = 1.0f / fmaxf(sqrtf(sm), 1e-12f);
    }
    __syncthreads();
    {
        float* outp = g_z + ((size_t)(b * DCH + c)) * T2 + t0 + 16 * h;
        #pragma unroll
        for (int t = 0; t < 16; ++t) {
            outp[t] = vals[t];
            g_znt[(size_t)(b * T2 + t0 + 16 * h + t) * DCH + c] = vals[t] * sinv[16 * h + t];
        }
    }
}

// ---------------- normalize embedding rows, store transposed [d][e] ----------------
__global__ void k_embnorm(const float* __restrict__ emb) {
    const int e    = blockIdx.x * 8 + (threadIdx.x >> 5);
    const int lane = threadIdx.x & 31;
    float4 v = *(const float4*)(emb + (size_t)e * DCH + lane * 4);
    float ss = v.x * v.x + v.y * v.y + v.z * v.z + v.w * v.w;
    #pragma unroll
    for (int o = 16; o > 0; o >>= 1) ss += __shfl_xor_sync(0xffffffffu, ss, o);
    float inv = 1.0f / fmaxf(sqrtf(ss), 1e-12f);
    g_embnT[(size_t)(lane * 4 + 0) * KCODE + e] = v.x * inv;
    g_embnT[(size_t)(lane * 4 + 1) * KCODE + e] = v.y * inv;
    g_embnT[(size_t)(lane * 4 + 2) * KCODE + e] = v.z * inv;
    g_embnT[(size_t)(lane * 4 + 3) * KCODE + e] = v.w * inv;
}

// ---------------- VQ GEMM + argmax, packed f32x2 (R4 — proven) ----------
__global__ __launch_bounds__(256) void k_vqgemm() {
    __shared__ float sA[128 * 64];   // [k][row] 32KB
    __shared__ float sB[16 * 128];   // [kk][c]   8KB
    const int tx   = threadIdx.x;
    const int row0 = blockIdx.x * 64;
    for (int it = tx; it < 2048; it += 256) {
        int row = it & 63, kq = it >> 6;
        float4 v = *(const float4*)&g_znt[(size_t)(row0 + row) * DCH + kq * 4];
        sA[(kq * 4 + 0) * 64 + row] = v.x;
        sA[(kq * 4 + 1) * 64 + row] = v.y;
        sA[(kq * 4 + 2) * 64 + row] = v.z;
        sA[(kq * 4 + 3) * 64 + row] = v.w;
    }
    const int tr = tx >> 5;
    const int tc = tx & 31;
    float best[8];
    int   bidx[8];
    #pragma unroll
    for (int i = 0; i < 8; ++i) { best[i] = -1e30f; bidx[i] = 0; }

    for (int ct = 0; ct < KCODE / 128; ++ct) {
        ull acc[4][4];
        #pragma unroll
        for (int p = 0; p < 4; ++p)
            #pragma unroll
            for (int j = 0; j < 4; ++j) acc[p][j] = 0ull;
        for (int kc = 0; kc < 8; ++kc) {
            __syncthreads();
            for (int it = tx; it < 512; it += 256) {
                int kk = it >> 5, c4 = it & 31;
                *(float4*)&sB[kk * 128 + c4 * 4] =
                    *(const float4*)&g_embnT[(size_t)(kc * 16 + kk) * KCODE + ct * 128 + c4 * 4];
            }
            __syncthreads();
            #pragma unroll 4
            for (int kk = 0; kk < 16; ++kk) {
                const int k = kc * 16 + kk;
                ulonglong2 aA = *(const ulonglong2*)&sA[k * 64 + tr * 8];
                ulonglong2 aB = *(const ulonglong2*)&sA[k * 64 + tr * 8 + 4];
                float4 bv = *(const float4*)&sB[kk * 128 + tc * 4];
                ull b0 = f2_dup(bv.x), b1 = f2_dup(bv.y);
                ull b2 = f2_dup(bv.z), b3 = f2_dup(bv.w);
                acc[0][0] = f2_fma(aA.x, b0, acc[0][0]);
                acc[0][1] = f2_fma(aA.x, b1, acc[0][1]);
                acc[0][2] = f2_fma(aA.x, b2, acc[0][2]);
                acc[0][3] = f2_fma(aA.x, b3, acc[0][3]);
                acc[1][0] = f2_fma(aA.y, b0, acc[1][0]);
                acc[1][1] = f2_fma(aA.y, b1, acc[1][1]);
                acc[1][2] = f2_fma(aA.y, b2, acc[1][2]);
                acc[1][3] = f2_fma(aA.y, b3, acc[1][3]);
                acc[2][0] = f2_fma(aB.x, b0, acc[2][0]);
                acc[2][1] = f2_fma(aB.x, b1, acc[2][1]);
                acc[2][2] = f2_fma(aB.x, b2, acc[2][2]);
                acc[2][3] = f2_fma(aB.x, b3, acc[2][3]);
                acc[3][0] = f2_fma(aB.y, b0, acc[3][0]);
                acc[3][1] = f2_fma(aB.y, b1, acc[3][1]);
                acc[3][2] = f2_fma(aB.y, b2, acc[3][2]);
                acc[3][3] = f2_fma(aB.y, b3, acc[3][3]);
            }
        }
        const int cbase = ct * 128 + tc * 4;
        #pragma unroll
        for (int p = 0; p < 4; ++p) {
            #pragma unroll
            for (int j = 0; j < 4; ++j) {
                float lo, hi;
                f2_unpack(acc[p][j], lo, hi);
                if (lo > best[2 * p + 0]) { best[2 * p + 0] = lo; bidx[2 * p + 0] = cbase + j; }
                if (hi > best[2 * p + 1]) { best[2 * p + 1] = hi; bidx[2 * p + 1] = cbase + j; }
            }
        }
    }
    #pragma unroll
    for (int o = 1; o < 32; o <<= 1) {
        #pragma unroll
        for (int i = 0; i < 8; ++i) {
            float ov = __shfl_xor_sync(0xffffffffu, best[i], o);
            int   oi = __shfl_xor_sync(0xffffffffu, bidx[i], o);
            if (ov > best[i] || (ov == best[i] && oi < bidx[i])) { best[i] = ov; bidx[i] = oi; }
        }
    }
    if (tc == 0) {
        #pragma unroll
        for (int i = 0; i < 8; ++i) g_idx[row0 + tr * 8 + i] = bidx[i];
    }
}

// ---------------- gather z_q + commitment-loss partial ----------------
__global__ void k_zq(const float* __restrict__ emb) {
    __shared__ float red[256];
    const size_t N = (size_t)BATCH * DCH * T2;
    float local = 0.f;
    size_t base = (size_t)blockIdx.x * 256 + threadIdx.x;
    for (int k = 0; k < 8; ++k) {
        size_t lin = base + (size_t)k * 524288;
        if (lin < N) {
            int t = (int)(lin & 8191);
            int d = (int)((lin >> 13) & 127);
            int b = (int)(lin >> 20);
            int e = g_idx[b * T2 + t];
            float q  = emb[(size_t)e * DCH + d];
            float zz = g_z[lin];
            g_zq[lin] = q;
            float df = zz - q;
            local += df * df;
        }
    }
    red[threadIdx.x] = local;
    __syncthreads();
    for (int o = 128; o > 0; o >>= 1) {
        if (threadIdx.x < o) red[threadIdx.x] += red[threadIdx.x + o];
        __syncthreads();
    }
    if (threadIdx.x == 0) atomicAdd(&g_acc[1], (double)red[0]);
}

// ---------------- convT1 (FFMA2, pre-paired global weights, 512 threads) ----------------
__global__ __launch_bounds__(512) void k_convT1(const float* __restrict__ bias) {
    __shared__ float sp[64 * 40];   // 64 ci-pairs x 18 positions x 2, row padded to 40
    const int b  = blockIdx.y;
    const int p0 = blockIdx.x * 64;
    const int i0 = p0 / 4 - 1;
    for (int i = threadIdx.x; i < 128 * 18; i += 512) {
        int ci = i / 18, li = i % 18;
        int ii = i0 + li;
        float v = (ii >= 0 && ii < T2) ? g_h[((size_t)(b * DCH + ci)) * T2 + ii] : 0.f;
        sp[(ci >> 1) * 40 + li * 2 + (ci & 1)] = v;
    }
    __syncthreads();
    const int co = threadIdx.x & 127;
    const int q  = threadIdx.x >> 7;
    ull acc2[16];
    #pragma unroll
    for (int t = 0; t < 16; ++t) acc2[t] = 0ull;

    for (int m = 0; m < 64; ++m) {
        ull pk[8];
        #pragma unroll
        for (int k = 0; k < 8; ++k) pk[k] = g_pwT[(m * 8 + k) * 128 + co];
        const ulonglong2* rw = (const ulonglong2*)((const ull*)(sp + m * 40) + 4 * q);
        ulonglong2 wA = rw[0], wB = rw[1], wC = rw[2];   // local positions 0..5
        ull pr[6] = {wA.x, wA.y, wB.x, wB.y, wC.x, wC.y};
        #pragma unroll
        for (int t = 0; t < 16; ++t) {
            const int r  = (t + 2) & 3;
            const int fb = ((t + 2) >> 2) + 1;
            acc2[t] = f2_fma(pr[fb - 1], pk[r + 4], acc2[t]);
            acc2[t] = f2_fma(pr[fb],     pk[r],     acc2[t]);
        }
    }
    float* outp = g_buf1 + ((size_t)(b * DCH + co)) * T1 + p0 + 16 * q;
    float bv = bias[co];
    #pragma unroll
    for (int t = 0; t < 16; ++t) {
        float lo, hi;
        f2_unpack(acc2[t], lo, hi);
        outp[t] = gelu_exact(bv + lo + hi);
    }
}

// ---------------- convT2 + tanh + write xr + rec-loss partial ----------------
__global__ void k_convT2(const float* __restrict__ w, const float* __restrict__ bias,
                         const float* __restrict__ x, float* __restrict__ out) {
    __shared__ float s[128 * 68];
    __shared__ float sw[1024];
    __shared__ float red[256];
    const int b  = blockIdx.y;
    const int p0 = blockIdx.x * 256;
    const int i0 = p0 / 4 - 1;
    for (int i = threadIdx.x; i < 128 * 66; i += 256) {
        int ci = i / 66, li = i % 66;
        int ii = i0 + li;
        s[ci * 68 + li] = (ii >= 0 && ii < T1) ? g_buf1[((size_t)(b * DCH + ci)) * T1 + ii] : 0.f;
    }
    for (int i = threadIdx.x; i < 1024; i += 256) sw[i] = w[i];
    __syncthreads();
    const int p  = p0 + threadIdx.x;
    const int r  = (p + 2) & 3;
    const int ib = ((p + 2) >> 2) - i0;
    const int ia = ib - 1;
    float acc = bias[0];
    for (int ci = 0; ci < 128; ++ci) {
        acc += sw[ci * 8 + r + 4] * s[ci * 68 + ia] + sw[ci * 8 + r] * s[ci * 68 + ib];
    }
    float xr = tanhf(acc);
    out[XR_OFF + (size_t)b * TLEN + p] = xr;
    float df = xr - x[(size_t)b * TLEN + p];
    red[threadIdx.x] = df * df;
    __syncthreads();
    for (int o = 128; o > 0; o >>= 1) {
        if (threadIdx.x < o) red[threadIdx.x] += red[threadIdx.x + o];
        __syncthreads();
    }
    if (threadIdx.x == 0) atomicAdd(&g_acc[0], (double)red[0]);
}

// ---------------- write idx as float ----------------
__global__ void k_idxout(float* __restrict__ out) {
    int i = blockIdx.x * 256 + threadIdx.x;
    if (i < NROWS) out[IDX_OFF + i] = (float)g_idx[i];
}

// ---------------- finalize scalars: rec, com, ppx ----------------
__global__ void k_final(const float* __restrict__ cs, float* __restrict__ out) {
    __shared__ float red[256];
    __shared__ float s_total;
    float part = 0.f;
    for (int i = threadIdx.x; i < KCODE; i += 256) part += cs[i];
    red[threadIdx.x] = part;
    __syncthreads();
    for (int o = 128; o > 0; o >>= 1) {
        if (threadIdx.x < o) red[threadIdx.x] += red[threadIdx.x + o];
        __syncthreads();
    }
    if (threadIdx.x == 0) s_total = red[0];
    __syncthreads();
    float denom = s_total + 1e-6f;
    float ent = 0.f;
    for (int i = threadIdx.x; i < KCODE; i += 256) {
        float n = cs[i] / denom;
        ent += n * logf(n + 1e-6f);
    }
    red[threadIdx.x] = ent;
    __syncthreads();
    for (int o = 128; o > 0; o >>= 1) {
        if (threadIdx.x < o) red[threadIdx.x] += red[threadIdx.x + o];
        __syncthreads();
    }
    if (threadIdx.x == 0) {
        out[0] = (float)(g_acc[0] / (double)((size_t)BATCH * TLEN));
        out[1] = (float)(g_acc[1] / (double)((size_t)BATCH * DCH * T2));
        out[2] = expf(-red[0]);
    }
}

// ---------------- launch ----------------
extern "C" void kernel_launch(void* const* d_in, const int* in_sizes, int n_in,
                              void* d_out, int out_size) {
    const float* x      = (const float*)d_in[0];
    const float* enc_w1 = (const float*)d_in[1];
    const float* enc_b1 = (const float*)d_in[2];
    const float* enc_w2 = (const float*)d_in[3];
    const float* enc_b2 = (const float*)d_in[4];
    const float* enc_w3 = (const float*)d_in[5];
    const float* enc_b3 = (const float*)d_in[6];
    const float* dec_w0 = (const float*)d_in[7];
    const float* dec_b0 = (const float*)d_in[8];
    const float* dec_wt1= (const float*)d_in[9];
    const float* dec_bt1= (const float*)d_in[10];
    const float* dec_wt2= (const float*)d_in[11];
    const float* dec_bt2= (const float*)d_in[12];
    const float* emb    = (const float*)d_in[13];
    const float* cs     = (const float*)d_in[14];
    float* out = (float*)d_out;

    k_zero<<<1, 32>>>();
    k_pack2<<<256, 256>>>(enc_w2);
    k_packT<<<256, 256>>>(dec_wt1);
    k_pack3<0><<<96, 256>>>(enc_w3);
    k_pack3<1><<<96, 256>>>(dec_w0);
    k_conv1<<<dim3(T1 / 256, BATCH), 256>>>(x, enc_w1, enc_b1);
    k_conv2<<<dim3(T2 / 16, BATCH), 128>>>(enc_b2);
    k_conv3<0><<<dim3(T2 / 32, BATCH), 256>>>(enc_b3);
    k_embnorm<<<KCODE / 8, 256>>>(emb);
    k_vqgemm<<<NROWS / 64, 256>>>();
    k_zq<<<2048, 256>>>(emb);
    k_conv3<1><<<dim3(T2 / 32, BATCH), 256>>>(dec_b0);
    k_convT1<<<dim3(T1 / 64, BATCH), 512>>>(dec_bt1);
    k_convT2<<<dim3(TLEN / 256, BATCH), 256>>>(dec_wt2, dec_bt2, x, out);
    k_idxout<<<NROWS / 256, 256>>>(out);
    k_final<<<1, 256>>>(cs, out);
}